// round 13
// baseline (speedup 1.0000x reference)
#include <cuda_runtime.h>
#include <cuda_bf16.h>
#include <math.h>
#include <cstdint>

#define BATCH 4
#define SEQ   2048
#define DIM   1024
#define HEADS 16
#define DH    64
#define INNER 1024
#define NFREQ 16
#define ROWS  (BATCH*SEQ)     // 8192
#define BH    (BATCH*HEADS)   // 64

// ---------------- scratch ----------------
__device__ __align__(256) float g_qkv [(size_t)ROWS * 3 * INNER];
__device__ __align__(256) float g_q   [(size_t)BH * SEQ * DH];   // tf32-rounded, pre-scaled 1/8
__device__ __align__(256) float g_k   [(size_t)BH * SEQ * DH];   // tf32-rounded
__device__ __align__(256) float g_v   [(size_t)BH * SEQ * DH];   // tf32-rounded
__device__ __align__(256) float g_attn[(size_t)ROWS * INNER];
__device__ __align__(256) float g_fenc[SEQ * DH];
__device__ __align__(256) float g_sinv[SEQ * 32];
__device__ __align__(256) float g_cosv[SEQ * 32];

// ---------------- helpers ----------------
__device__ __forceinline__ unsigned f2t(float x) {
    unsigned u; asm("cvt.rna.tf32.f32 %0, %1;" : "=r"(u) : "f"(x)); return u;
}
__device__ __forceinline__ void mma8(float* c, const unsigned* a, const unsigned* b) {
    asm volatile(
        "mma.sync.aligned.m16n8k8.row.col.f32.tf32.tf32.f32 "
        "{%0,%1,%2,%3},{%4,%5,%6,%7},{%8,%9},{%0,%1,%2,%3};"
        : "+f"(c[0]), "+f"(c[1]), "+f"(c[2]), "+f"(c[3])
        : "r"(a[0]), "r"(a[1]), "r"(a[2]), "r"(a[3]), "r"(b[0]), "r"(b[1]));
}
__device__ __forceinline__ void cpa16(void* smem, const void* gmem) {
    unsigned s = (unsigned)__cvta_generic_to_shared(smem);
    asm volatile("cp.async.cg.shared.global [%0], [%1], 16;" :: "r"(s), "l"(gmem));
}
__device__ __forceinline__ void cpa_commit() { asm volatile("cp.async.commit_group;"); }
template<int N> __device__ __forceinline__ void cpa_wait() {
    asm volatile("cp.async.wait_group %0;" :: "n"(N));
}

// ---------------- table kernel ----------------
__global__ void table_kernel(const float* __restrict__ w_fproj,
                             const float* __restrict__ b_fproj) {
    int p = blockIdx.x;
    int d = threadIdx.x;
    float fp = (float)p;
    float acc = b_fproj[d];
#pragma unroll
    for (int j = 0; j < NFREQ; j++) {
        float s = sinf(fp * (float)(j + 1));
        float c = cosf(fp * (float)(j + 1));
        acc += s * w_fproj[d * (2 * NFREQ) + j] + c * w_fproj[d * (2 * NFREQ) + NFREQ + j];
    }
    g_fenc[p * DH + d] = acc;
    if (d < 32) {
        float freq = powf(10000.0f, -(float)d / 32.0f);
        float ang = fp * freq;
        g_sinv[p * 32 + d] = sinf(ang);
        g_cosv[p * 32 + d] = cosf(ang);
    }
}

// ---------------- RoPE + rearrange + tf32 pre-round (R6-proven) ----------------
__global__ void __launch_bounds__(256)
rope_kernel() {
    int idx = blockIdx.x * 256 + threadIdx.x;
    int d = idx & 63;
    int h = (idx >> 6) & 15;
    int n = (idx >> 10) & 2047;
    int b = idx >> 21;
    const float* row = g_qkv + (size_t)(b * SEQ + n) * (3 * INNER);
    int col = h * DH + d;
    float cosv = g_cosv[n * 32 + (d >> 1)];
    float sinv = g_sinv[n * 32 + (d >> 1)];
    float fe   = g_fenc[n * DH + d];
    int pidx; float sgn;
    if (d < 32) { pidx = 2 * d + 1;    sgn = -1.0f; }
    else        { pidx = 2 * (d - 32); sgn =  1.0f; }
    float qv = row[col];
    float qp = row[h * DH + pidx];
    float kv = row[INNER + col];
    float kp = row[INNER + h * DH + pidx];
    float vv = row[2 * INNER + col];
    int bh = b * HEADS + h;
    size_t o = ((size_t)bh * SEQ + n) * DH + d;
    g_q[o] = __uint_as_float(f2t(0.125f * (qv * cosv + sgn * qp * sinv + fe)));
    g_k[o] = __uint_as_float(f2t(kv * cosv + sgn * kp * sinv + fe));
    g_v[o] = __uint_as_float(f2t(vv));
}

// ---------------- tf32 GEMM, 128x256x16 tile, cp.async double-buffered ----------------
// 256 threads = 8 warps (4 M-rows x 2 N-cols), warp tile 32x128.
#define GS 20
#define GEMM_SMEM ((2*128*GS + 2*256*GS) * 4)   // 61440 B

template<bool BIAS>
__global__ void __launch_bounds__(256)
gemm_tf32(const float* __restrict__ A, const float* __restrict__ Bw,
          const float* __restrict__ bias, float* __restrict__ C,
          int M, int N, int K) {
    extern __shared__ float gsm[];
    float* As = gsm;                  // [2][128*GS]
    float* Bs = gsm + 2 * 128 * GS;   // [2][256*GS]
    const int tid = threadIdx.x;
    const int lane = tid & 31, wid = tid >> 5;
    const int g = lane >> 2, q = lane & 3;
    const int wr = wid >> 1, wc = wid & 1;
    const int bm = blockIdx.y * 128, bn = blockIdx.x * 256;
    const int lrow = tid >> 2, lcol = (tid & 3) * 4;   // 64 rows per pass

    float acc[2][16][4];
#pragma unroll
    for (int mt = 0; mt < 2; mt++)
#pragma unroll
        for (int nt = 0; nt < 16; nt++)
#pragma unroll
            for (int i = 0; i < 4; i++) acc[mt][nt][i] = 0.0f;

    auto stage = [&](int buf, int k0) {
        float* ab = As + buf * 128 * GS;
        float* bb = Bs + buf * 256 * GS;
        cpa16(ab + lrow        * GS + lcol, A  + (size_t)(bm + lrow)        * K + k0 + lcol);
        cpa16(ab + (lrow + 64) * GS + lcol, A  + (size_t)(bm + lrow + 64)   * K + k0 + lcol);
#pragma unroll
        for (int p = 0; p < 4; p++)
            cpa16(bb + (lrow + p * 64) * GS + lcol,
                  Bw + (size_t)(bn + lrow + p * 64) * K + k0 + lcol);
        cpa_commit();
    };

    stage(0, 0);
    for (int k0 = 0; k0 < K; k0 += 16) {
        int cur = (k0 >> 4) & 1;
        if (k0 + 16 < K) { stage(cur ^ 1, k0 + 16); cpa_wait<1>(); }
        else             { cpa_wait<0>(); }
        __syncthreads();
        const float* ab = As + cur * 128 * GS;
        const float* bb = Bs + cur * 256 * GS;
#pragma unroll
        for (int ks = 0; ks < 2; ks++) {
            unsigned af[2][4];
#pragma unroll
            for (int mt = 0; mt < 2; mt++) {
                int r = wr * 32 + mt * 16;
                af[mt][0] = f2t(ab[(r + g)     * GS + ks * 8 + q]);
                af[mt][1] = f2t(ab[(r + g + 8) * GS + ks * 8 + q]);
                af[mt][2] = f2t(ab[(r + g)     * GS + ks * 8 + q + 4]);
                af[mt][3] = f2t(ab[(r + g + 8) * GS + ks * 8 + q + 4]);
            }
#pragma unroll
            for (int nt = 0; nt < 16; nt++) {
                int c = wc * 128 + nt * 8;
                unsigned bf[2];
                bf[0] = f2t(bb[(c + g) * GS + ks * 8 + q]);
                bf[1] = f2t(bb[(c + g) * GS + ks * 8 + q + 4]);
#pragma unroll
                for (int mt = 0; mt < 2; mt++)
                    mma8(acc[mt][nt], af[mt], bf);
            }
        }
        __syncthreads();
    }

#pragma unroll
    for (int mt = 0; mt < 2; mt++) {
        int r = bm + wr * 32 + mt * 16 + g;
#pragma unroll
        for (int nt = 0; nt < 16; nt++) {
            int cc = bn + wc * 128 + nt * 8 + 2 * q;
            float b0 = 0.0f, b1 = 0.0f;
            if (BIAS) { b0 = bias[cc]; b1 = bias[cc + 1]; }
            *(float2*)(C + (size_t)r * N + cc) =
                make_float2(acc[mt][nt][0] + b0, acc[mt][nt][1] + b1);
            *(float2*)(C + (size_t)(r + 8) * N + cc) =
                make_float2(acc[mt][nt][2] + b0, acc[mt][nt][3] + b1);
        }
    }
}

// ---------------- flash attention v5 (R6-proven, unchanged) ----------------
#define SQ 68
#define SK 68
#define SV 72
#define NT (SEQ / 64)
#define FLASH_SMEM ((128*SQ + 2*64*SK + 2*64*SV) * 4)   // 106496 B

__global__ void __launch_bounds__(128, 2)
flash_tc(float* __restrict__ out) {
    extern __shared__ char smraw[];
    float* Qs = (float*)smraw;
    float* Kb = (float*)(smraw + 128 * SQ * 4);
    float* Vb = Kb + 2 * 64 * SK;

    const int tid = threadIdx.x, lane = tid & 31, wid = tid >> 5;
    const int g = lane >> 2, q = lane & 3;
    const int bh = blockIdx.y, qt = blockIdx.x;
    const size_t base = (size_t)bh * SEQ * DH;
    const float* qg = g_q + base + (size_t)qt * 128 * DH;
    const float* kg0 = g_k + base;
    const float* vg0 = g_v + base;
    const int lrow = tid >> 4, lcol = (tid & 15) * 4;

#pragma unroll
    for (int j = 0; j < 16; j++) {
        int row = lrow + j * 8;
        cpa16(Qs + row * SQ + lcol, qg + row * DH + lcol);
    }
    cpa_commit();

    auto stage = [&](int buf, int kt) {
        float* kb = Kb + buf * 64 * SK;
        float* vb = Vb + buf * 64 * SV;
        const float* kg = kg0 + (size_t)kt * 64 * DH;
        const float* vg = vg0 + (size_t)kt * 64 * DH;
#pragma unroll
        for (int j = 0; j < 8; j++) {
            int row = lrow + j * 8;
            cpa16(kb + row * SK + lcol, kg + row * DH + lcol);
            cpa16(vb + row * SV + lcol, vg + row * DH + lcol);
        }
        cpa_commit();
    };

    float o[2][8][4];
#pragma unroll
    for (int mt = 0; mt < 2; mt++)
#pragma unroll
        for (int nt = 0; nt < 8; nt++)
#pragma unroll
            for (int i = 0; i < 4; i++) o[mt][nt][i] = 0.0f;
    float m0[2] = {-1e30f, -1e30f}, m1[2] = {-1e30f, -1e30f};
    float l0[2] = {0.0f, 0.0f},     l1[2] = {0.0f, 0.0f};
    const int qr = wid * 32;
    const int srcA = (lane & ~3) + (q >> 1);
    const int srcB = srcA + 2;
    const bool odd = q & 1;

    stage(0, 0);
    for (int kt = 0; kt < NT; kt++) {
        int cur = kt & 1;
        if (kt + 1 < NT) { stage(cur ^ 1, kt + 1); cpa_wait<1>(); }
        else             { cpa_wait<0>(); }
        __syncthreads();
        const float* kb = Kb + cur * 64 * SK;
        const float* vb = Vb + cur * 64 * SV;

        float s[2][8][4];
#pragma unroll
        for (int mt = 0; mt < 2; mt++)
#pragma unroll
            for (int nt = 0; nt < 8; nt++)
#pragma unroll
                for (int i = 0; i < 4; i++) s[mt][nt][i] = 0.0f;
#pragma unroll
        for (int kc = 0; kc < 8; kc++) {
            unsigned bf[8][2];
#pragma unroll
            for (int nt = 0; nt < 8; nt++) {
                bf[nt][0] = __float_as_uint(kb[(nt * 8 + g) * SK + kc * 8 + q]);
                bf[nt][1] = __float_as_uint(kb[(nt * 8 + g) * SK + kc * 8 + q + 4]);
            }
#pragma unroll
            for (int mt = 0; mt < 2; mt++) {
                int r = qr + mt * 16;
                unsigned af[4];
                af[0] = __float_as_uint(Qs[(r + g)     * SQ + kc * 8 + q]);
                af[1] = __float_as_uint(Qs[(r + g + 8) * SQ + kc * 8 + q]);
                af[2] = __float_as_uint(Qs[(r + g)     * SQ + kc * 8 + q + 4]);
                af[3] = __float_as_uint(Qs[(r + g + 8) * SQ + kc * 8 + q + 4]);
#pragma unroll
                for (int nt = 0; nt < 8; nt++)
                    mma8(s[mt][nt], af, bf[nt]);
            }
        }

#pragma unroll
        for (int mt = 0; mt < 2; mt++) {
            float rm0 = -1e30f, rm1 = -1e30f;
#pragma unroll
            for (int nt = 0; nt < 8; nt++) {
                rm0 = fmaxf(rm0, fmaxf(s[mt][nt][0], s[mt][nt][1]));
                rm1 = fmaxf(rm1, fmaxf(s[mt][nt][2], s[mt][nt][3]));
            }
            rm0 = fmaxf(rm0, __shfl_xor_sync(0xffffffffu, rm0, 1));
            rm0 = fmaxf(rm0, __shfl_xor_sync(0xffffffffu, rm0, 2));
            rm1 = fmaxf(rm1, __shfl_xor_sync(0xffffffffu, rm1, 1));
            rm1 = fmaxf(rm1, __shfl_xor_sync(0xffffffffu, rm1, 2));
            float mn0 = fmaxf(m0[mt], rm0), mn1 = fmaxf(m1[mt], rm1);
            float c0 = __expf(m0[mt] - mn0), c1 = __expf(m1[mt] - mn1);
            m0[mt] = mn0; m1[mt] = mn1;
            float rs0 = 0.0f, rs1 = 0.0f;
#pragma unroll
            for (int nt = 0; nt < 8; nt++) {
                s[mt][nt][0] = __expf(s[mt][nt][0] - mn0);
                s[mt][nt][1] = __expf(s[mt][nt][1] - mn0);
                s[mt][nt][2] = __expf(s[mt][nt][2] - mn1);
                s[mt][nt][3] = __expf(s[mt][nt][3] - mn1);
                rs0 += s[mt][nt][0] + s[mt][nt][1];
                rs1 += s[mt][nt][2] + s[mt][nt][3];
            }
            rs0 += __shfl_xor_sync(0xffffffffu, rs0, 1);
            rs0 += __shfl_xor_sync(0xffffffffu, rs0, 2);
            rs1 += __shfl_xor_sync(0xffffffffu, rs1, 1);
            rs1 += __shfl_xor_sync(0xffffffffu, rs1, 2);
            l0[mt] = l0[mt] * c0 + rs0;
            l1[mt] = l1[mt] * c1 + rs1;
#pragma unroll
            for (int nt = 0; nt < 8; nt++) {
                o[mt][nt][0] *= c0; o[mt][nt][1] *= c0;
                o[mt][nt][2] *= c1; o[mt][nt][3] *= c1;
            }
        }

#pragma unroll
        for (int kc = 0; kc < 8; kc++) {
            unsigned bfv[8][2];
#pragma unroll
            for (int nt = 0; nt < 8; nt++) {
                bfv[nt][0] = __float_as_uint(vb[(kc * 8 + q)     * SV + nt * 8 + g]);
                bfv[nt][1] = __float_as_uint(vb[(kc * 8 + q + 4) * SV + nt * 8 + g]);
            }
#pragma unroll
            for (int mt = 0; mt < 2; mt++) {
                float e0 = __shfl_sync(0xffffffffu, s[mt][kc][0], srcA);
                float e1 = __shfl_sync(0xffffffffu, s[mt][kc][1], srcA);
                float e2 = __shfl_sync(0xffffffffu, s[mt][kc][2], srcA);
                float e3 = __shfl_sync(0xffffffffu, s[mt][kc][3], srcA);
                float f0 = __shfl_sync(0xffffffffu, s[mt][kc][0], srcB);
                float f1 = __shfl_sync(0xffffffffu, s[mt][kc][1], srcB);
                float f2 = __shfl_sync(0xffffffffu, s[mt][kc][2], srcB);
                float f3 = __shfl_sync(0xffffffffu, s[mt][kc][3], srcB);
                unsigned af[4];
                af[0] = f2t(odd ? e1 : e0);
                af[1] = f2t(odd ? e3 : e2);
                af[2] = f2t(odd ? f1 : f0);
                af[3] = f2t(odd ? f3 : f2);
#pragma unroll
                for (int nt = 0; nt < 8; nt++)
                    mma8(o[mt][nt], af, bfv[nt]);
            }
        }
        __syncthreads();
    }

    // epilogue
    int b = bh >> 4, h = bh & 15;
#pragma unroll
    for (int mt = 0; mt < 2; mt++) {
        float il0 = 1.0f / l0[mt], il1 = 1.0f / l1[mt];
        int r0 = qt * 128 + qr + mt * 16 + g;
#pragma unroll
        for (int nt = 0; nt < 8; nt++) {
            int cc = h * DH + nt * 8 + 2 * q;
            *(float2*)(out + (size_t)(b * SEQ + r0) * INNER + cc) =
                make_float2(o[mt][nt][0] * il0, o[mt][nt][1] * il0);
            *(float2*)(out + (size_t)(b * SEQ + r0 + 8) * INNER + cc) =
                make_float2(o[mt][nt][2] * il1, o[mt][nt][3] * il1);
        }
    }
}

// ---------------- launch ----------------
extern "C" void kernel_launch(void* const* d_in, const int* in_sizes, int n_in,
                              void* d_out, int out_size) {
    const float* x       = (const float*)d_in[0];
    const float* w_qkv   = (const float*)d_in[1];
    const float* w_fproj = (const float*)d_in[2];
    const float* b_fproj = (const float*)d_in[3];
    const float* w_out   = (const float*)d_in[4];
    const float* b_out   = (const float*)d_in[5];
    float* out = (float*)d_out;

    float *qkv_p, *attn_p;
    cudaGetSymbolAddress((void**)&qkv_p,  g_qkv);
    cudaGetSymbolAddress((void**)&attn_p, g_attn);

    cudaFuncSetAttribute(gemm_tf32<false>, cudaFuncAttributeMaxDynamicSharedMemorySize, GEMM_SMEM);
    cudaFuncSetAttribute(gemm_tf32<true>,  cudaFuncAttributeMaxDynamicSharedMemorySize, GEMM_SMEM);
    cudaFuncSetAttribute(flash_tc, cudaFuncAttributeMaxDynamicSharedMemorySize, FLASH_SMEM);

    table_kernel<<<SEQ, DH>>>(w_fproj, b_fproj);

    {   // QKV: [8192,3072] = x @ w_qkv^T   (128x256 tiles)
        dim3 grid(3 * INNER / 256, ROWS / 128);   // 12 x 64
        gemm_tf32<false><<<grid, 256, GEMM_SMEM>>>(x, w_qkv, nullptr, qkv_p, ROWS, 3 * INNER, DIM);
    }

    rope_kernel<<<(BATCH * SEQ * HEADS * DH) / 256, 256>>>();

    {   // flash attention
        dim3 grid(SEQ / 128, BH);
        flash_tc<<<grid, 128, FLASH_SMEM>>>(attn_p);
    }

    {   // out projection: [8192,1024] = attn @ w_out^T + b_out
        dim3 grid(DIM / 256, ROWS / 128);         // 4 x 64
        gemm_tf32<true><<<grid, 256, GEMM_SMEM>>>(attn_p, w_out, b_out, out, ROWS, DIM, INNER);
    }
}

// round 14
// speedup vs baseline: 1.0493x; 1.0493x over previous
#include <cuda_runtime.h>
#include <cuda_bf16.h>
#include <math.h>
#include <cstdint>

#define BATCH 4
#define SEQ   2048
#define DIM   1024
#define HEADS 16
#define DH    64
#define INNER 1024
#define NFREQ 16
#define ROWS  (BATCH*SEQ)     // 8192
#define BH    (BATCH*HEADS)   // 64

// ---------------- scratch ----------------
__device__ __align__(256) float g_qkv [(size_t)ROWS * 3 * INNER];
__device__ __align__(256) float g_q   [(size_t)BH * SEQ * DH];   // tf32-rounded, pre-scaled 1/8
__device__ __align__(256) float g_k   [(size_t)BH * SEQ * DH];   // tf32-rounded
__device__ __align__(256) float g_v   [(size_t)BH * SEQ * DH];   // tf32-rounded
__device__ __align__(256) float g_attn[(size_t)ROWS * INNER];
__device__ __align__(256) float g_fenc[SEQ * DH];
__device__ __align__(256) float g_sinv[SEQ * 32];
__device__ __align__(256) float g_cosv[SEQ * 32];

// ---------------- helpers ----------------
__device__ __forceinline__ unsigned f2t(float x) {
    unsigned u; asm("cvt.rna.tf32.f32 %0, %1;" : "=r"(u) : "f"(x)); return u;
}
__device__ __forceinline__ void mma8(float* c, const unsigned* a, const unsigned* b) {
    asm volatile(
        "mma.sync.aligned.m16n8k8.row.col.f32.tf32.tf32.f32 "
        "{%0,%1,%2,%3},{%4,%5,%6,%7},{%8,%9},{%0,%1,%2,%3};"
        : "+f"(c[0]), "+f"(c[1]), "+f"(c[2]), "+f"(c[3])
        : "r"(a[0]), "r"(a[1]), "r"(a[2]), "r"(a[3]), "r"(b[0]), "r"(b[1]));
}
__device__ __forceinline__ void cpa16(void* smem, const void* gmem) {
    unsigned s = (unsigned)__cvta_generic_to_shared(smem);
    asm volatile("cp.async.cg.shared.global [%0], [%1], 16;" :: "r"(s), "l"(gmem));
}
__device__ __forceinline__ void cpa_commit() { asm volatile("cp.async.commit_group;"); }
template<int N> __device__ __forceinline__ void cpa_wait() {
    asm volatile("cp.async.wait_group %0;" :: "n"(N));
}

// ---------------- table kernel (4 positions per 256-thread block) ----------------
__global__ void __launch_bounds__(256)
table_kernel(const float* __restrict__ w_fproj,
             const float* __restrict__ b_fproj) {
    int p = blockIdx.x * 4 + (threadIdx.x >> 6);
    int d = threadIdx.x & 63;
    float fp = (float)p;
    float acc = b_fproj[d];
#pragma unroll
    for (int j = 0; j < NFREQ; j++) {
        float s = sinf(fp * (float)(j + 1));
        float c = cosf(fp * (float)(j + 1));
        acc += s * w_fproj[d * (2 * NFREQ) + j] + c * w_fproj[d * (2 * NFREQ) + NFREQ + j];
    }
    g_fenc[p * DH + d] = acc;
    if (d < 32) {
        float freq = powf(10000.0f, -(float)d / 32.0f);
        float ang = fp * freq;
        g_sinv[p * 32 + d] = sinf(ang);
        g_cosv[p * 32 + d] = cosf(ang);
    }
}

// ---------------- RoPE + rearrange + tf32 pre-round (R6-proven) ----------------
__global__ void __launch_bounds__(256)
rope_kernel() {
    int idx = blockIdx.x * 256 + threadIdx.x;
    int d = idx & 63;
    int h = (idx >> 6) & 15;
    int n = (idx >> 10) & 2047;
    int b = idx >> 21;
    const float* row = g_qkv + (size_t)(b * SEQ + n) * (3 * INNER);
    int col = h * DH + d;
    float cosv = g_cosv[n * 32 + (d >> 1)];
    float sinv = g_sinv[n * 32 + (d >> 1)];
    float fe   = g_fenc[n * DH + d];
    int pidx; float sgn;
    if (d < 32) { pidx = 2 * d + 1;    sgn = -1.0f; }
    else        { pidx = 2 * (d - 32); sgn =  1.0f; }
    float qv = row[col];
    float qp = row[h * DH + pidx];
    float kv = row[INNER + col];
    float kp = row[INNER + h * DH + pidx];
    float vv = row[2 * INNER + col];
    int bh = b * HEADS + h;
    size_t o = ((size_t)bh * SEQ + n) * DH + d;
    g_q[o] = __uint_as_float(f2t(0.125f * (qv * cosv + sgn * qp * sinv + fe)));
    g_k[o] = __uint_as_float(f2t(kv * cosv + sgn * kp * sinv + fe));
    g_v[o] = __uint_as_float(f2t(vv));
}

// ---------------- tf32 GEMM, 128x128x16, cp.async double-buffered (R6-proven) ----------------
#define GS 20
#define GEMM_SMEM (2 * 2 * 128 * GS * 4)   // 81920 B

template<bool BIAS>
__global__ void __launch_bounds__(256, 2)
gemm_tf32(const float* __restrict__ A, const float* __restrict__ Bw,
          const float* __restrict__ bias, float* __restrict__ C,
          int M, int N, int K) {
    extern __shared__ float gsm[];
    float* As = gsm;
    float* Bs = gsm + 2 * 128 * GS;
    const int tid = threadIdx.x;
    const int lane = tid & 31, wid = tid >> 5;
    const int g = lane >> 2, q = lane & 3;
    const int wr = wid >> 1, wc = wid & 1;
    const int bm = blockIdx.y * 128, bn = blockIdx.x * 128;
    const int lrow = tid >> 2, lcol = (tid & 3) * 4;
    const int lrow2 = lrow + 64;

    float acc[2][8][4];
#pragma unroll
    for (int mt = 0; mt < 2; mt++)
#pragma unroll
        for (int nt = 0; nt < 8; nt++)
#pragma unroll
            for (int i = 0; i < 4; i++) acc[mt][nt][i] = 0.0f;

    auto stage = [&](int buf, int k0) {
        float* ab = As + buf * 128 * GS;
        float* bb = Bs + buf * 128 * GS;
        cpa16(ab + lrow  * GS + lcol, A  + (size_t)(bm + lrow)  * K + k0 + lcol);
        cpa16(ab + lrow2 * GS + lcol, A  + (size_t)(bm + lrow2) * K + k0 + lcol);
        cpa16(bb + lrow  * GS + lcol, Bw + (size_t)(bn + lrow)  * K + k0 + lcol);
        cpa16(bb + lrow2 * GS + lcol, Bw + (size_t)(bn + lrow2) * K + k0 + lcol);
        cpa_commit();
    };

    stage(0, 0);
    for (int k0 = 0; k0 < K; k0 += 16) {
        int cur = (k0 >> 4) & 1;
        if (k0 + 16 < K) { stage(cur ^ 1, k0 + 16); cpa_wait<1>(); }
        else             { cpa_wait<0>(); }
        __syncthreads();
        const float* ab = As + cur * 128 * GS;
        const float* bb = Bs + cur * 128 * GS;
#pragma unroll
        for (int ks = 0; ks < 2; ks++) {
            unsigned af[2][4], bf[8][2];
#pragma unroll
            for (int mt = 0; mt < 2; mt++) {
                int r = wr * 32 + mt * 16;
                af[mt][0] = f2t(ab[(r + g)     * GS + ks * 8 + q]);
                af[mt][1] = f2t(ab[(r + g + 8) * GS + ks * 8 + q]);
                af[mt][2] = f2t(ab[(r + g)     * GS + ks * 8 + q + 4]);
                af[mt][3] = f2t(ab[(r + g + 8) * GS + ks * 8 + q + 4]);
            }
#pragma unroll
            for (int nt = 0; nt < 8; nt++) {
                int c = wc * 64 + nt * 8;
                bf[nt][0] = f2t(bb[(c + g) * GS + ks * 8 + q]);
                bf[nt][1] = f2t(bb[(c + g) * GS + ks * 8 + q + 4]);
            }
#pragma unroll
            for (int mt = 0; mt < 2; mt++)
#pragma unroll
                for (int nt = 0; nt < 8; nt++)
                    mma8(acc[mt][nt], af[mt], bf[nt]);
        }
        __syncthreads();
    }

#pragma unroll
    for (int mt = 0; mt < 2; mt++) {
        int r = bm + wr * 32 + mt * 16 + g;
#pragma unroll
        for (int nt = 0; nt < 8; nt++) {
            int cc = bn + wc * 64 + nt * 8 + 2 * q;
            float b0 = 0.0f, b1 = 0.0f;
            if (BIAS) { b0 = bias[cc]; b1 = bias[cc + 1]; }
            *(float2*)(C + (size_t)r * N + cc) =
                make_float2(acc[mt][nt][0] + b0, acc[mt][nt][1] + b1);
            *(float2*)(C + (size_t)(r + 8) * N + cc) =
                make_float2(acc[mt][nt][2] + b0, acc[mt][nt][3] + b1);
        }
    }
}

// ---------------- flash attention v6: lazy rescale (bit-identical) ----------------
#define SQ 68
#define SK 68
#define SV 72
#define NT (SEQ / 64)
#define FLASH_SMEM ((128*SQ + 2*64*SK + 2*64*SV) * 4)   // 106496 B

__global__ void __launch_bounds__(128, 2)
flash_tc(float* __restrict__ out) {
    extern __shared__ char smraw[];
    float* Qs = (float*)smraw;
    float* Kb = (float*)(smraw + 128 * SQ * 4);
    float* Vb = Kb + 2 * 64 * SK;

    const int tid = threadIdx.x, lane = tid & 31, wid = tid >> 5;
    const int g = lane >> 2, q = lane & 3;
    const int bh = blockIdx.y, qt = blockIdx.x;
    const size_t base = (size_t)bh * SEQ * DH;
    const float* qg = g_q + base + (size_t)qt * 128 * DH;
    const float* kg0 = g_k + base;
    const float* vg0 = g_v + base;
    const int lrow = tid >> 4, lcol = (tid & 15) * 4;

#pragma unroll
    for (int j = 0; j < 16; j++) {
        int row = lrow + j * 8;
        cpa16(Qs + row * SQ + lcol, qg + row * DH + lcol);
    }
    cpa_commit();

    auto stage = [&](int buf, int kt) {
        float* kb = Kb + buf * 64 * SK;
        float* vb = Vb + buf * 64 * SV;
        const float* kg = kg0 + (size_t)kt * 64 * DH;
        const float* vg = vg0 + (size_t)kt * 64 * DH;
#pragma unroll
        for (int j = 0; j < 8; j++) {
            int row = lrow + j * 8;
            cpa16(kb + row * SK + lcol, kg + row * DH + lcol);
            cpa16(vb + row * SV + lcol, vg + row * DH + lcol);
        }
        cpa_commit();
    };

    float o[2][8][4];
#pragma unroll
    for (int mt = 0; mt < 2; mt++)
#pragma unroll
        for (int nt = 0; nt < 8; nt++)
#pragma unroll
            for (int i = 0; i < 4; i++) o[mt][nt][i] = 0.0f;
    float m0[2] = {-1e30f, -1e30f}, m1[2] = {-1e30f, -1e30f};
    float l0[2] = {0.0f, 0.0f},     l1[2] = {0.0f, 0.0f};
    const int qr = wid * 32;
    const int srcA = (lane & ~3) + (q >> 1);
    const int srcB = srcA + 2;
    const bool odd = q & 1;

    stage(0, 0);
    for (int kt = 0; kt < NT; kt++) {
        int cur = kt & 1;
        if (kt + 1 < NT) { stage(cur ^ 1, kt + 1); cpa_wait<1>(); }
        else             { cpa_wait<0>(); }
        __syncthreads();
        const float* kb = Kb + cur * 64 * SK;
        const float* vb = Vb + cur * 64 * SV;

        float s[2][8][4];
#pragma unroll
        for (int mt = 0; mt < 2; mt++)
#pragma unroll
            for (int nt = 0; nt < 8; nt++)
#pragma unroll
                for (int i = 0; i < 4; i++) s[mt][nt][i] = 0.0f;
#pragma unroll
        for (int kc = 0; kc < 8; kc++) {
            unsigned bf[8][2];
#pragma unroll
            for (int nt = 0; nt < 8; nt++) {
                bf[nt][0] = __float_as_uint(kb[(nt * 8 + g) * SK + kc * 8 + q]);
                bf[nt][1] = __float_as_uint(kb[(nt * 8 + g) * SK + kc * 8 + q + 4]);
            }
#pragma unroll
            for (int mt = 0; mt < 2; mt++) {
                int r = qr + mt * 16;
                unsigned af[4];
                af[0] = __float_as_uint(Qs[(r + g)     * SQ + kc * 8 + q]);
                af[1] = __float_as_uint(Qs[(r + g + 8) * SQ + kc * 8 + q]);
                af[2] = __float_as_uint(Qs[(r + g)     * SQ + kc * 8 + q + 4]);
                af[3] = __float_as_uint(Qs[(r + g + 8) * SQ + kc * 8 + q + 4]);
#pragma unroll
                for (int nt = 0; nt < 8; nt++)
                    mma8(s[mt][nt], af, bf[nt]);
            }
        }

        // online softmax with lazy (bit-identical) rescale
#pragma unroll
        for (int mt = 0; mt < 2; mt++) {
            float rm0 = m0[mt], rm1 = m1[mt];   // seed with running max
#pragma unroll
            for (int nt = 0; nt < 8; nt++) {
                rm0 = fmaxf(rm0, fmaxf(s[mt][nt][0], s[mt][nt][1]));
                rm1 = fmaxf(rm1, fmaxf(s[mt][nt][2], s[mt][nt][3]));
            }
            rm0 = fmaxf(rm0, __shfl_xor_sync(0xffffffffu, rm0, 1));
            rm0 = fmaxf(rm0, __shfl_xor_sync(0xffffffffu, rm0, 2));
            rm1 = fmaxf(rm1, __shfl_xor_sync(0xffffffffu, rm1, 1));
            rm1 = fmaxf(rm1, __shfl_xor_sync(0xffffffffu, rm1, 2));
            float mn0 = rm0, mn1 = rm1;         // == fmax(m_old, tile max)
            float rs0 = 0.0f, rs1 = 0.0f;
#pragma unroll
            for (int nt = 0; nt < 8; nt++) {
                s[mt][nt][0] = __expf(s[mt][nt][0] - mn0);
                s[mt][nt][1] = __expf(s[mt][nt][1] - mn0);
                s[mt][nt][2] = __expf(s[mt][nt][2] - mn1);
                s[mt][nt][3] = __expf(s[mt][nt][3] - mn1);
                rs0 += s[mt][nt][0] + s[mt][nt][1];
                rs1 += s[mt][nt][2] + s[mt][nt][3];
            }
            rs0 += __shfl_xor_sync(0xffffffffu, rs0, 1);
            rs0 += __shfl_xor_sync(0xffffffffu, rs0, 2);
            rs1 += __shfl_xor_sync(0xffffffffu, rs1, 1);
            rs1 += __shfl_xor_sync(0xffffffffu, rs1, 2);
            if (mn0 != m0[mt] || mn1 != m1[mt]) {
                // max moved: rescale (c == expf(0) == 1 cases are excluded exactly)
                float c0 = __expf(m0[mt] - mn0), c1 = __expf(m1[mt] - mn1);
                m0[mt] = mn0; m1[mt] = mn1;
                l0[mt] = l0[mt] * c0 + rs0;
                l1[mt] = l1[mt] * c1 + rs1;
#pragma unroll
                for (int nt = 0; nt < 8; nt++) {
                    o[mt][nt][0] *= c0; o[mt][nt][1] *= c0;
                    o[mt][nt][2] *= c1; o[mt][nt][3] *= c1;
                }
            } else {
                // max unchanged: l*1+rs and o*1 are bit-identical to this
                l0[mt] = l0[mt] * 1.0f + rs0;
                l1[mt] = l1[mt] * 1.0f + rs1;
            }
        }

        // O += P V  — P fragments via shfl (C-layout -> A-layout)
#pragma unroll
        for (int kc = 0; kc < 8; kc++) {
            unsigned bfv[8][2];
#pragma unroll
            for (int nt = 0; nt < 8; nt++) {
                bfv[nt][0] = __float_as_uint(vb[(kc * 8 + q)     * SV + nt * 8 + g]);
                bfv[nt][1] = __float_as_uint(vb[(kc * 8 + q + 4) * SV + nt * 8 + g]);
            }
#pragma unroll
            for (int mt = 0; mt < 2; mt++) {
                float e0 = __shfl_sync(0xffffffffu, s[mt][kc][0], srcA);
                float e1 = __shfl_sync(0xffffffffu, s[mt][kc][1], srcA);
                float e2 = __shfl_sync(0xffffffffu, s[mt][kc][2], srcA);
                float e3 = __shfl_sync(0xffffffffu, s[mt][kc][3], srcA);
                float f0 = __shfl_sync(0xffffffffu, s[mt][kc][0], srcB);
                float f1 = __shfl_sync(0xffffffffu, s[mt][kc][1], srcB);
                float f2 = __shfl_sync(0xffffffffu, s[mt][kc][2], srcB);
                float f3 = __shfl_sync(0xffffffffu, s[mt][kc][3], srcB);
                unsigned af[4];
                af[0] = f2t(odd ? e1 : e0);
                af[1] = f2t(odd ? e3 : e2);
                af[2] = f2t(odd ? f1 : f0);
                af[3] = f2t(odd ? f3 : f2);
#pragma unroll
                for (int nt = 0; nt < 8; nt++)
                    mma8(o[mt][nt], af, bfv[nt]);
            }
        }
        __syncthreads();
    }

    // epilogue
    int b = bh >> 4, h = bh & 15;
#pragma unroll
    for (int mt = 0; mt < 2; mt++) {
        float il0 = 1.0f / l0[mt], il1 = 1.0f / l1[mt];
        int r0 = qt * 128 + qr + mt * 16 + g;
#pragma unroll
        for (int nt = 0; nt < 8; nt++) {
            int cc = h * DH + nt * 8 + 2 * q;
            *(float2*)(out + (size_t)(b * SEQ + r0) * INNER + cc) =
                make_float2(o[mt][nt][0] * il0, o[mt][nt][1] * il0);
            *(float2*)(out + (size_t)(b * SEQ + r0 + 8) * INNER + cc) =
                make_float2(o[mt][nt][2] * il1, o[mt][nt][3] * il1);
        }
    }
}

// ---------------- launch ----------------
extern "C" void kernel_launch(void* const* d_in, const int* in_sizes, int n_in,
                              void* d_out, int out_size) {
    const float* x       = (const float*)d_in[0];
    const float* w_qkv   = (const float*)d_in[1];
    const float* w_fproj = (const float*)d_in[2];
    const float* b_fproj = (const float*)d_in[3];
    const float* w_out   = (const float*)d_in[4];
    const float* b_out   = (const float*)d_in[5];
    float* out = (float*)d_out;

    float *qkv_p, *attn_p;
    cudaGetSymbolAddress((void**)&qkv_p,  g_qkv);
    cudaGetSymbolAddress((void**)&attn_p, g_attn);

    cudaFuncSetAttribute(gemm_tf32<false>, cudaFuncAttributeMaxDynamicSharedMemorySize, GEMM_SMEM);
    cudaFuncSetAttribute(gemm_tf32<true>,  cudaFuncAttributeMaxDynamicSharedMemorySize, GEMM_SMEM);
    cudaFuncSetAttribute(flash_tc, cudaFuncAttributeMaxDynamicSharedMemorySize, FLASH_SMEM);

    table_kernel<<<SEQ / 4, 256>>>(w_fproj, b_fproj);

    {   // QKV: [8192,3072] = x @ w_qkv^T   (128x128 tiles, R6-proven)
        dim3 grid(3 * INNER / 128, ROWS / 128);   // 24 x 64
        gemm_tf32<false><<<grid, 256, GEMM_SMEM>>>(x, w_qkv, nullptr, qkv_p, ROWS, 3 * INNER, DIM);
    }

    rope_kernel<<<(BATCH * SEQ * HEADS * DH) / 256, 256>>>();

    {   // flash attention
        dim3 grid(SEQ / 128, BH);
        flash_tc<<<grid, 128, FLASH_SMEM>>>(attn_p);
    }

    {   // out projection
        dim3 grid(DIM / 128, ROWS / 128);
        gemm_tf32<true><<<grid, 256, GEMM_SMEM>>>(attn_p, w_out, b_out, out, ROWS, DIM, INNER);
    }
}

// round 15
// speedup vs baseline: 1.0650x; 1.0150x over previous
#include <cuda_runtime.h>
#include <cuda_bf16.h>
#include <math.h>
#include <cstdint>

#define BATCH 4
#define SEQ   2048
#define DIM   1024
#define HEADS 16
#define DH    64
#define INNER 1024
#define NFREQ 16
#define ROWS  (BATCH*SEQ)     // 8192
#define BH    (BATCH*HEADS)   // 64

// ---------------- scratch ----------------
__device__ __align__(256) float g_qkv [(size_t)ROWS * 3 * INNER];
__device__ __align__(256) float g_q   [(size_t)BH * SEQ * DH];   // tf32-rounded, pre-scaled 1/8
__device__ __align__(256) float g_k   [(size_t)BH * SEQ * DH];   // tf32-rounded
__device__ __align__(256) float g_v   [(size_t)BH * SEQ * DH];   // tf32-rounded
__device__ __align__(256) float g_attn[(size_t)ROWS * INNER];
__device__ __align__(256) float g_fenc[SEQ * DH];
__device__ __align__(256) float g_sinv[SEQ * 32];
__device__ __align__(256) float g_cosv[SEQ * 32];

// ---------------- helpers ----------------
__device__ __forceinline__ unsigned f2t(float x) {
    unsigned u; asm("cvt.rna.tf32.f32 %0, %1;" : "=r"(u) : "f"(x)); return u;
}
__device__ __forceinline__ void mma8(float* c, const unsigned* a, const unsigned* b) {
    asm volatile(
        "mma.sync.aligned.m16n8k8.row.col.f32.tf32.tf32.f32 "
        "{%0,%1,%2,%3},{%4,%5,%6,%7},{%8,%9},{%0,%1,%2,%3};"
        : "+f"(c[0]), "+f"(c[1]), "+f"(c[2]), "+f"(c[3])
        : "r"(a[0]), "r"(a[1]), "r"(a[2]), "r"(a[3]), "r"(b[0]), "r"(b[1]));
}
__device__ __forceinline__ void cpa16(void* smem, const void* gmem) {
    unsigned s = (unsigned)__cvta_generic_to_shared(smem);
    asm volatile("cp.async.cg.shared.global [%0], [%1], 16;" :: "r"(s), "l"(gmem));
}
__device__ __forceinline__ void cpa_commit() { asm volatile("cp.async.commit_group;"); }
template<int N> __device__ __forceinline__ void cpa_wait() {
    asm volatile("cp.async.wait_group %0;" :: "n"(N));
}

// ---------------- table kernel (4 positions per 256-thread block) ----------------
__global__ void __launch_bounds__(256)
table_kernel(const float* __restrict__ w_fproj,
             const float* __restrict__ b_fproj) {
    int p = blockIdx.x * 4 + (threadIdx.x >> 6);
    int d = threadIdx.x & 63;
    float fp = (float)p;
    float acc = b_fproj[d];
#pragma unroll
    for (int j = 0; j < NFREQ; j++) {
        float s = sinf(fp * (float)(j + 1));
        float c = cosf(fp * (float)(j + 1));
        acc += s * w_fproj[d * (2 * NFREQ) + j] + c * w_fproj[d * (2 * NFREQ) + NFREQ + j];
    }
    g_fenc[p * DH + d] = acc;
    if (d < 32) {
        float freq = powf(10000.0f, -(float)d / 32.0f);
        float ang = fp * freq;
        g_sinv[p * 32 + d] = sinf(ang);
        g_cosv[p * 32 + d] = cosf(ang);
    }
}

// ---------------- RoPE + rearrange + tf32 pre-round (R6-proven) ----------------
__global__ void __launch_bounds__(256)
rope_kernel() {
    int idx = blockIdx.x * 256 + threadIdx.x;
    int d = idx & 63;
    int h = (idx >> 6) & 15;
    int n = (idx >> 10) & 2047;
    int b = idx >> 21;
    const float* row = g_qkv + (size_t)(b * SEQ + n) * (3 * INNER);
    int col = h * DH + d;
    float cosv = g_cosv[n * 32 + (d >> 1)];
    float sinv = g_sinv[n * 32 + (d >> 1)];
    float fe   = g_fenc[n * DH + d];
    int pidx; float sgn;
    if (d < 32) { pidx = 2 * d + 1;    sgn = -1.0f; }
    else        { pidx = 2 * (d - 32); sgn =  1.0f; }
    float qv = row[col];
    float qp = row[h * DH + pidx];
    float kv = row[INNER + col];
    float kp = row[INNER + h * DH + pidx];
    float vv = row[2 * INNER + col];
    int bh = b * HEADS + h;
    size_t o = ((size_t)bh * SEQ + n) * DH + d;
    g_q[o] = __uint_as_float(f2t(0.125f * (qv * cosv + sgn * qp * sinv + fe)));
    g_k[o] = __uint_as_float(f2t(kv * cosv + sgn * kp * sinv + fe));
    g_v[o] = __uint_as_float(f2t(vv));
}

// ---------------- tf32 GEMM, 128x128x16, cp.async double-buffered (R6-proven) ----------------
#define GS 20
#define GEMM_SMEM (2 * 2 * 128 * GS * 4)   // 81920 B

template<bool BIAS>
__global__ void __launch_bounds__(256, 2)
gemm_tf32(const float* __restrict__ A, const float* __restrict__ Bw,
          const float* __restrict__ bias, float* __restrict__ C,
          int M, int N, int K) {
    extern __shared__ float gsm[];
    float* As = gsm;
    float* Bs = gsm + 2 * 128 * GS;
    const int tid = threadIdx.x;
    const int lane = tid & 31, wid = tid >> 5;
    const int g = lane >> 2, q = lane & 3;
    const int wr = wid >> 1, wc = wid & 1;
    const int bm = blockIdx.y * 128, bn = blockIdx.x * 128;
    const int lrow = tid >> 2, lcol = (tid & 3) * 4;
    const int lrow2 = lrow + 64;

    float acc[2][8][4];
#pragma unroll
    for (int mt = 0; mt < 2; mt++)
#pragma unroll
        for (int nt = 0; nt < 8; nt++)
#pragma unroll
            for (int i = 0; i < 4; i++) acc[mt][nt][i] = 0.0f;

    auto stage = [&](int buf, int k0) {
        float* ab = As + buf * 128 * GS;
        float* bb = Bs + buf * 128 * GS;
        cpa16(ab + lrow  * GS + lcol, A  + (size_t)(bm + lrow)  * K + k0 + lcol);
        cpa16(ab + lrow2 * GS + lcol, A  + (size_t)(bm + lrow2) * K + k0 + lcol);
        cpa16(bb + lrow  * GS + lcol, Bw + (size_t)(bn + lrow)  * K + k0 + lcol);
        cpa16(bb + lrow2 * GS + lcol, Bw + (size_t)(bn + lrow2) * K + k0 + lcol);
        cpa_commit();
    };

    stage(0, 0);
    for (int k0 = 0; k0 < K; k0 += 16) {
        int cur = (k0 >> 4) & 1;
        if (k0 + 16 < K) { stage(cur ^ 1, k0 + 16); cpa_wait<1>(); }
        else             { cpa_wait<0>(); }
        __syncthreads();
        const float* ab = As + cur * 128 * GS;
        const float* bb = Bs + cur * 128 * GS;
#pragma unroll
        for (int ks = 0; ks < 2; ks++) {
            unsigned af[2][4], bf[8][2];
#pragma unroll
            for (int mt = 0; mt < 2; mt++) {
                int r = wr * 32 + mt * 16;
                af[mt][0] = f2t(ab[(r + g)     * GS + ks * 8 + q]);
                af[mt][1] = f2t(ab[(r + g + 8) * GS + ks * 8 + q]);
                af[mt][2] = f2t(ab[(r + g)     * GS + ks * 8 + q + 4]);
                af[mt][3] = f2t(ab[(r + g + 8) * GS + ks * 8 + q + 4]);
            }
#pragma unroll
            for (int nt = 0; nt < 8; nt++) {
                int c = wc * 64 + nt * 8;
                bf[nt][0] = f2t(bb[(c + g) * GS + ks * 8 + q]);
                bf[nt][1] = f2t(bb[(c + g) * GS + ks * 8 + q + 4]);
            }
#pragma unroll
            for (int mt = 0; mt < 2; mt++)
#pragma unroll
                for (int nt = 0; nt < 8; nt++)
                    mma8(acc[mt][nt], af[mt], bf[nt]);
        }
        __syncthreads();
    }

#pragma unroll
    for (int mt = 0; mt < 2; mt++) {
        int r = bm + wr * 32 + mt * 16 + g;
#pragma unroll
        for (int nt = 0; nt < 8; nt++) {
            int cc = bn + wc * 64 + nt * 8 + 2 * q;
            float b0 = 0.0f, b1 = 0.0f;
            if (BIAS) { b0 = bias[cc]; b1 = bias[cc + 1]; }
            *(float2*)(C + (size_t)r * N + cc) =
                make_float2(acc[mt][nt][0] + b0, acc[mt][nt][1] + b1);
            *(float2*)(C + (size_t)(r + 8) * N + cc) =
                make_float2(acc[mt][nt][2] + b0, acc[mt][nt][3] + b1);
        }
    }
}

// ---------------- flash attention v5 (exact R6 kernel) ----------------
#define SQ 68
#define SK 68
#define SV 72
#define NT (SEQ / 64)
#define FLASH_SMEM ((128*SQ + 2*64*SK + 2*64*SV) * 4)   // 106496 B

__global__ void __launch_bounds__(128, 2)
flash_tc(float* __restrict__ out) {
    extern __shared__ char smraw[];
    float* Qs = (float*)smraw;
    float* Kb = (float*)(smraw + 128 * SQ * 4);
    float* Vb = Kb + 2 * 64 * SK;

    const int tid = threadIdx.x, lane = tid & 31, wid = tid >> 5;
    const int g = lane >> 2, q = lane & 3;
    const int bh = blockIdx.y, qt = blockIdx.x;
    const size_t base = (size_t)bh * SEQ * DH;
    const float* qg = g_q + base + (size_t)qt * 128 * DH;
    const float* kg0 = g_k + base;
    const float* vg0 = g_v + base;
    const int lrow = tid >> 4, lcol = (tid & 15) * 4;

#pragma unroll
    for (int j = 0; j < 16; j++) {
        int row = lrow + j * 8;
        cpa16(Qs + row * SQ + lcol, qg + row * DH + lcol);
    }
    cpa_commit();

    auto stage = [&](int buf, int kt) {
        float* kb = Kb + buf * 64 * SK;
        float* vb = Vb + buf * 64 * SV;
        const float* kg = kg0 + (size_t)kt * 64 * DH;
        const float* vg = vg0 + (size_t)kt * 64 * DH;
#pragma unroll
        for (int j = 0; j < 8; j++) {
            int row = lrow + j * 8;
            cpa16(kb + row * SK + lcol, kg + row * DH + lcol);
            cpa16(vb + row * SV + lcol, vg + row * DH + lcol);
        }
        cpa_commit();
    };

    float o[2][8][4];
#pragma unroll
    for (int mt = 0; mt < 2; mt++)
#pragma unroll
        for (int nt = 0; nt < 8; nt++)
#pragma unroll
            for (int i = 0; i < 4; i++) o[mt][nt][i] = 0.0f;
    float m0[2] = {-1e30f, -1e30f}, m1[2] = {-1e30f, -1e30f};
    float l0[2] = {0.0f, 0.0f},     l1[2] = {0.0f, 0.0f};
    const int qr = wid * 32;
    const int srcA = (lane & ~3) + (q >> 1);
    const int srcB = srcA + 2;
    const bool odd = q & 1;

    stage(0, 0);
    for (int kt = 0; kt < NT; kt++) {
        int cur = kt & 1;
        if (kt + 1 < NT) { stage(cur ^ 1, kt + 1); cpa_wait<1>(); }
        else             { cpa_wait<0>(); }
        __syncthreads();
        const float* kb = Kb + cur * 64 * SK;
        const float* vb = Vb + cur * 64 * SV;

        float s[2][8][4];
#pragma unroll
        for (int mt = 0; mt < 2; mt++)
#pragma unroll
            for (int nt = 0; nt < 8; nt++)
#pragma unroll
                for (int i = 0; i < 4; i++) s[mt][nt][i] = 0.0f;
#pragma unroll
        for (int kc = 0; kc < 8; kc++) {
            unsigned bf[8][2];
#pragma unroll
            for (int nt = 0; nt < 8; nt++) {
                bf[nt][0] = __float_as_uint(kb[(nt * 8 + g) * SK + kc * 8 + q]);
                bf[nt][1] = __float_as_uint(kb[(nt * 8 + g) * SK + kc * 8 + q + 4]);
            }
#pragma unroll
            for (int mt = 0; mt < 2; mt++) {
                int r = qr + mt * 16;
                unsigned af[4];
                af[0] = __float_as_uint(Qs[(r + g)     * SQ + kc * 8 + q]);
                af[1] = __float_as_uint(Qs[(r + g + 8) * SQ + kc * 8 + q]);
                af[2] = __float_as_uint(Qs[(r + g)     * SQ + kc * 8 + q + 4]);
                af[3] = __float_as_uint(Qs[(r + g + 8) * SQ + kc * 8 + q + 4]);
#pragma unroll
                for (int nt = 0; nt < 8; nt++)
                    mma8(s[mt][nt], af, bf[nt]);
            }
        }

#pragma unroll
        for (int mt = 0; mt < 2; mt++) {
            float rm0 = -1e30f, rm1 = -1e30f;
#pragma unroll
            for (int nt = 0; nt < 8; nt++) {
                rm0 = fmaxf(rm0, fmaxf(s[mt][nt][0], s[mt][nt][1]));
                rm1 = fmaxf(rm1, fmaxf(s[mt][nt][2], s[mt][nt][3]));
            }
            rm0 = fmaxf(rm0, __shfl_xor_sync(0xffffffffu, rm0, 1));
            rm0 = fmaxf(rm0, __shfl_xor_sync(0xffffffffu, rm0, 2));
            rm1 = fmaxf(rm1, __shfl_xor_sync(0xffffffffu, rm1, 1));
            rm1 = fmaxf(rm1, __shfl_xor_sync(0xffffffffu, rm1, 2));
            float mn0 = fmaxf(m0[mt], rm0), mn1 = fmaxf(m1[mt], rm1);
            float c0 = __expf(m0[mt] - mn0), c1 = __expf(m1[mt] - mn1);
            m0[mt] = mn0; m1[mt] = mn1;
            float rs0 = 0.0f, rs1 = 0.0f;
#pragma unroll
            for (int nt = 0; nt < 8; nt++) {
                s[mt][nt][0] = __expf(s[mt][nt][0] - mn0);
                s[mt][nt][1] = __expf(s[mt][nt][1] - mn0);
                s[mt][nt][2] = __expf(s[mt][nt][2] - mn1);
                s[mt][nt][3] = __expf(s[mt][nt][3] - mn1);
                rs0 += s[mt][nt][0] + s[mt][nt][1];
                rs1 += s[mt][nt][2] + s[mt][nt][3];
            }
            rs0 += __shfl_xor_sync(0xffffffffu, rs0, 1);
            rs0 += __shfl_xor_sync(0xffffffffu, rs0, 2);
            rs1 += __shfl_xor_sync(0xffffffffu, rs1, 1);
            rs1 += __shfl_xor_sync(0xffffffffu, rs1, 2);
            l0[mt] = l0[mt] * c0 + rs0;
            l1[mt] = l1[mt] * c1 + rs1;
#pragma unroll
            for (int nt = 0; nt < 8; nt++) {
                o[mt][nt][0] *= c0; o[mt][nt][1] *= c0;
                o[mt][nt][2] *= c1; o[mt][nt][3] *= c1;
            }
        }

#pragma unroll
        for (int kc = 0; kc < 8; kc++) {
            unsigned bfv[8][2];
#pragma unroll
            for (int nt = 0; nt < 8; nt++) {
                bfv[nt][0] = __float_as_uint(vb[(kc * 8 + q)     * SV + nt * 8 + g]);
                bfv[nt][1] = __float_as_uint(vb[(kc * 8 + q + 4) * SV + nt * 8 + g]);
            }
#pragma unroll
            for (int mt = 0; mt < 2; mt++) {
                float e0 = __shfl_sync(0xffffffffu, s[mt][kc][0], srcA);
                float e1 = __shfl_sync(0xffffffffu, s[mt][kc][1], srcA);
                float e2 = __shfl_sync(0xffffffffu, s[mt][kc][2], srcA);
                float e3 = __shfl_sync(0xffffffffu, s[mt][kc][3], srcA);
                float f0 = __shfl_sync(0xffffffffu, s[mt][kc][0], srcB);
                float f1 = __shfl_sync(0xffffffffu, s[mt][kc][1], srcB);
                float f2 = __shfl_sync(0xffffffffu, s[mt][kc][2], srcB);
                float f3 = __shfl_sync(0xffffffffu, s[mt][kc][3], srcB);
                unsigned af[4];
                af[0] = f2t(odd ? e1 : e0);
                af[1] = f2t(odd ? e3 : e2);
                af[2] = f2t(odd ? f1 : f0);
                af[3] = f2t(odd ? f3 : f2);
#pragma unroll
                for (int nt = 0; nt < 8; nt++)
                    mma8(o[mt][nt], af, bfv[nt]);
            }
        }
        __syncthreads();
    }

    // epilogue
    int b = bh >> 4, h = bh & 15;
#pragma unroll
    for (int mt = 0; mt < 2; mt++) {
        float il0 = 1.0f / l0[mt], il1 = 1.0f / l1[mt];
        int r0 = qt * 128 + qr + mt * 16 + g;
#pragma unroll
        for (int nt = 0; nt < 8; nt++) {
            int cc = h * DH + nt * 8 + 2 * q;
            *(float2*)(out + (size_t)(b * SEQ + r0) * INNER + cc) =
                make_float2(o[mt][nt][0] * il0, o[mt][nt][1] * il0);
            *(float2*)(out + (size_t)(b * SEQ + r0 + 8) * INNER + cc) =
                make_float2(o[mt][nt][2] * il1, o[mt][nt][3] * il1);
        }
    }
}

// ---------------- launch ----------------
extern "C" void kernel_launch(void* const* d_in, const int* in_sizes, int n_in,
                              void* d_out, int out_size) {
    const float* x       = (const float*)d_in[0];
    const float* w_qkv   = (const float*)d_in[1];
    const float* w_fproj = (const float*)d_in[2];
    const float* b_fproj = (const float*)d_in[3];
    const float* w_out   = (const float*)d_in[4];
    const float* b_out   = (const float*)d_in[5];
    float* out = (float*)d_out;

    float *qkv_p, *attn_p;
    cudaGetSymbolAddress((void**)&qkv_p,  g_qkv);
    cudaGetSymbolAddress((void**)&attn_p, g_attn);

    cudaFuncSetAttribute(gemm_tf32<false>, cudaFuncAttributeMaxDynamicSharedMemorySize, GEMM_SMEM);
    cudaFuncSetAttribute(gemm_tf32<true>,  cudaFuncAttributeMaxDynamicSharedMemorySize, GEMM_SMEM);
    cudaFuncSetAttribute(flash_tc, cudaFuncAttributeMaxDynamicSharedMemorySize, FLASH_SMEM);

    table_kernel<<<SEQ / 4, 256>>>(w_fproj, b_fproj);

    {   // QKV: [8192,3072] = x @ w_qkv^T
        dim3 grid(3 * INNER / 128, ROWS / 128);   // 24 x 64
        gemm_tf32<false><<<grid, 256, GEMM_SMEM>>>(x, w_qkv, nullptr, qkv_p, ROWS, 3 * INNER, DIM);
    }

    rope_kernel<<<(BATCH * SEQ * HEADS * DH) / 256, 256>>>();

    {   // flash attention
        dim3 grid(SEQ / 128, BH);
        flash_tc<<<grid, 128, FLASH_SMEM>>>(attn_p);
    }

    {   // out projection
        dim3 grid(DIM / 128, ROWS / 128);
        gemm_tf32<true><<<grid, 256, GEMM_SMEM>>>(attn_p, w_out, b_out, out, ROWS, DIM, INNER);
    }
}

// round 16
// speedup vs baseline: 1.0947x; 1.0279x over previous
#include <cuda_runtime.h>
#include <cuda_bf16.h>
#include <math.h>
#include <cstdint>

#define BATCH 4
#define SEQ   2048
#define DIM   1024
#define HEADS 16
#define DH    64
#define INNER 1024
#define NFREQ 16
#define ROWS  (BATCH*SEQ)     // 8192
#define BH    (BATCH*HEADS)   // 64

// ---------------- scratch ----------------
__device__ __align__(256) float g_qkv [(size_t)ROWS * 3 * INNER];
__device__ __align__(256) float g_q   [(size_t)BH * SEQ * DH];   // tf32-rounded, pre-scaled 1/8
__device__ __align__(256) float g_k   [(size_t)BH * SEQ * DH];   // tf32-rounded
__device__ __align__(256) float g_v   [(size_t)BH * SEQ * DH];   // tf32-rounded
__device__ __align__(256) float g_attn[(size_t)ROWS * INNER];
__device__ __align__(256) float g_fenc[SEQ * DH];
__device__ __align__(256) float g_sinv[SEQ * 32];
__device__ __align__(256) float g_cosv[SEQ * 32];

// ---------------- helpers ----------------
__device__ __forceinline__ unsigned f2t(float x) {
    unsigned u; asm("cvt.rna.tf32.f32 %0, %1;" : "=r"(u) : "f"(x)); return u;
}
__device__ __forceinline__ void mma8(float* c, const unsigned* a, const unsigned* b) {
    asm volatile(
        "mma.sync.aligned.m16n8k8.row.col.f32.tf32.tf32.f32 "
        "{%0,%1,%2,%3},{%4,%5,%6,%7},{%8,%9},{%0,%1,%2,%3};"
        : "+f"(c[0]), "+f"(c[1]), "+f"(c[2]), "+f"(c[3])
        : "r"(a[0]), "r"(a[1]), "r"(a[2]), "r"(a[3]), "r"(b[0]), "r"(b[1]));
}
__device__ __forceinline__ void cpa16(void* smem, const void* gmem) {
    unsigned s = (unsigned)__cvta_generic_to_shared(smem);
    asm volatile("cp.async.cg.shared.global [%0], [%1], 16;" :: "r"(s), "l"(gmem));
}
__device__ __forceinline__ void cpa_commit() { asm volatile("cp.async.commit_group;"); }
template<int N> __device__ __forceinline__ void cpa_wait() {
    asm volatile("cp.async.wait_group %0;" :: "n"(N));
}

// ---------------- table kernel (4 positions per 256-thread block) ----------------
__global__ void __launch_bounds__(256)
table_kernel(const float* __restrict__ w_fproj,
             const float* __restrict__ b_fproj) {
    int p = blockIdx.x * 4 + (threadIdx.x >> 6);
    int d = threadIdx.x & 63;
    float fp = (float)p;
    float acc = b_fproj[d];
#pragma unroll
    for (int j = 0; j < NFREQ; j++) {
        float s = sinf(fp * (float)(j + 1));
        float c = cosf(fp * (float)(j + 1));
        acc += s * w_fproj[d * (2 * NFREQ) + j] + c * w_fproj[d * (2 * NFREQ) + NFREQ + j];
    }
    g_fenc[p * DH + d] = acc;
    if (d < 32) {
        float freq = powf(10000.0f, -(float)d / 32.0f);
        float ang = fp * freq;
        g_sinv[p * 32 + d] = sinf(ang);
        g_cosv[p * 32 + d] = cosf(ang);
    }
}

// ---------------- RoPE + rearrange + tf32 pre-round (R6-proven) ----------------
__global__ void __launch_bounds__(256)
rope_kernel() {
    int idx = blockIdx.x * 256 + threadIdx.x;
    int d = idx & 63;
    int h = (idx >> 6) & 15;
    int n = (idx >> 10) & 2047;
    int b = idx >> 21;
    const float* row = g_qkv + (size_t)(b * SEQ + n) * (3 * INNER);
    int col = h * DH + d;
    float cosv = g_cosv[n * 32 + (d >> 1)];
    float sinv = g_sinv[n * 32 + (d >> 1)];
    float fe   = g_fenc[n * DH + d];
    int pidx; float sgn;
    if (d < 32) { pidx = 2 * d + 1;    sgn = -1.0f; }
    else        { pidx = 2 * (d - 32); sgn =  1.0f; }
    float qv = row[col];
    float qp = row[h * DH + pidx];
    float kv = row[INNER + col];
    float kp = row[INNER + h * DH + pidx];
    float vv = row[2 * INNER + col];
    int bh = b * HEADS + h;
    size_t o = ((size_t)bh * SEQ + n) * DH + d;
    g_q[o] = __uint_as_float(f2t(0.125f * (qv * cosv + sgn * qp * sinv + fe)));
    g_k[o] = __uint_as_float(f2t(kv * cosv + sgn * kp * sinv + fe));
    g_v[o] = __uint_as_float(f2t(vv));
}

// ---------------- tf32 GEMM, 128x128x32, cp.async double-buffered ----------------
// BK=32: half the block barriers of BK=16, deeper cp.async MLP per stage.
// K-slice order fed to mma8 is identical to BK=16 -> bit-identical accumulation.
#define GS 36   // 32 + 4 padding; fragment LDS conflict-free (4*g+q mod 32 distinct)
#define GEMM_SMEM (2 * 2 * 128 * GS * 4)   // 73728 B -> 2 blocks/SM

template<bool BIAS>
__global__ void __launch_bounds__(256, 2)
gemm_tf32(const float* __restrict__ A, const float* __restrict__ Bw,
          const float* __restrict__ bias, float* __restrict__ C,
          int M, int N, int K) {
    extern __shared__ float gsm[];
    float* As = gsm;
    float* Bs = gsm + 2 * 128 * GS;
    const int tid = threadIdx.x;
    const int lane = tid & 31, wid = tid >> 5;
    const int g = lane >> 2, q = lane & 3;
    const int wr = wid >> 1, wc = wid & 1;
    const int bm = blockIdx.y * 128, bn = blockIdx.x * 128;
    const int lrow = tid >> 3, lcol = (tid & 7) * 4;   // 32 rows x 32 cols per pass

    float acc[2][8][4];
#pragma unroll
    for (int mt = 0; mt < 2; mt++)
#pragma unroll
        for (int nt = 0; nt < 8; nt++)
#pragma unroll
            for (int i = 0; i < 4; i++) acc[mt][nt][i] = 0.0f;

    auto stage = [&](int buf, int k0) {
        float* ab = As + buf * 128 * GS;
        float* bb = Bs + buf * 128 * GS;
#pragma unroll
        for (int j = 0; j < 4; j++) {
            int row = lrow + j * 32;
            cpa16(ab + row * GS + lcol, A  + (size_t)(bm + row) * K + k0 + lcol);
            cpa16(bb + row * GS + lcol, Bw + (size_t)(bn + row) * K + k0 + lcol);
        }
        cpa_commit();
    };

    stage(0, 0);
    for (int k0 = 0; k0 < K; k0 += 32) {
        int cur = (k0 >> 5) & 1;
        if (k0 + 32 < K) { stage(cur ^ 1, k0 + 32); cpa_wait<1>(); }
        else             { cpa_wait<0>(); }
        __syncthreads();
        const float* ab = As + cur * 128 * GS;
        const float* bb = Bs + cur * 128 * GS;
#pragma unroll
        for (int ks = 0; ks < 4; ks++) {
            unsigned af[2][4], bf[8][2];
#pragma unroll
            for (int mt = 0; mt < 2; mt++) {
                int r = wr * 32 + mt * 16;
                af[mt][0] = f2t(ab[(r + g)     * GS + ks * 8 + q]);
                af[mt][1] = f2t(ab[(r + g + 8) * GS + ks * 8 + q]);
                af[mt][2] = f2t(ab[(r + g)     * GS + ks * 8 + q + 4]);
                af[mt][3] = f2t(ab[(r + g + 8) * GS + ks * 8 + q + 4]);
            }
#pragma unroll
            for (int nt = 0; nt < 8; nt++) {
                int c = wc * 64 + nt * 8;
                bf[nt][0] = f2t(bb[(c + g) * GS + ks * 8 + q]);
                bf[nt][1] = f2t(bb[(c + g) * GS + ks * 8 + q + 4]);
            }
#pragma unroll
            for (int mt = 0; mt < 2; mt++)
#pragma unroll
                for (int nt = 0; nt < 8; nt++)
                    mma8(acc[mt][nt], af[mt], bf[nt]);
        }
        __syncthreads();
    }

#pragma unroll
    for (int mt = 0; mt < 2; mt++) {
        int r = bm + wr * 32 + mt * 16 + g;
#pragma unroll
        for (int nt = 0; nt < 8; nt++) {
            int cc = bn + wc * 64 + nt * 8 + 2 * q;
            float b0 = 0.0f, b1 = 0.0f;
            if (BIAS) { b0 = bias[cc]; b1 = bias[cc + 1]; }
            *(float2*)(C + (size_t)r * N + cc) =
                make_float2(acc[mt][nt][0] + b0, acc[mt][nt][1] + b1);
            *(float2*)(C + (size_t)(r + 8) * N + cc) =
                make_float2(acc[mt][nt][2] + b0, acc[mt][nt][3] + b1);
        }
    }
}

// ---------------- flash attention v5 (exact R6/R15 kernel) ----------------
#define SQ 68
#define SK 68
#define SV 72
#define NT (SEQ / 64)
#define FLASH_SMEM ((128*SQ + 2*64*SK + 2*64*SV) * 4)   // 106496 B

__global__ void __launch_bounds__(128, 2)
flash_tc(float* __restrict__ out) {
    extern __shared__ char smraw[];
    float* Qs = (float*)smraw;
    float* Kb = (float*)(smraw + 128 * SQ * 4);
    float* Vb = Kb + 2 * 64 * SK;

    const int tid = threadIdx.x, lane = tid & 31, wid = tid >> 5;
    const int g = lane >> 2, q = lane & 3;
    const int bh = blockIdx.y, qt = blockIdx.x;
    const size_t base = (size_t)bh * SEQ * DH;
    const float* qg = g_q + base + (size_t)qt * 128 * DH;
    const float* kg0 = g_k + base;
    const float* vg0 = g_v + base;
    const int lrow = tid >> 4, lcol = (tid & 15) * 4;

#pragma unroll
    for (int j = 0; j < 16; j++) {
        int row = lrow + j * 8;
        cpa16(Qs + row * SQ + lcol, qg + row * DH + lcol);
    }
    cpa_commit();

    auto stage = [&](int buf, int kt) {
        float* kb = Kb + buf * 64 * SK;
        float* vb = Vb + buf * 64 * SV;
        const float* kg = kg0 + (size_t)kt * 64 * DH;
        const float* vg = vg0 + (size_t)kt * 64 * DH;
#pragma unroll
        for (int j = 0; j < 8; j++) {
            int row = lrow + j * 8;
            cpa16(kb + row * SK + lcol, kg + row * DH + lcol);
            cpa16(vb + row * SV + lcol, vg + row * DH + lcol);
        }
        cpa_commit();
    };

    float o[2][8][4];
#pragma unroll
    for (int mt = 0; mt < 2; mt++)
#pragma unroll
        for (int nt = 0; nt < 8; nt++)
#pragma unroll
            for (int i = 0; i < 4; i++) o[mt][nt][i] = 0.0f;
    float m0[2] = {-1e30f, -1e30f}, m1[2] = {-1e30f, -1e30f};
    float l0[2] = {0.0f, 0.0f},     l1[2] = {0.0f, 0.0f};
    const int qr = wid * 32;
    const int srcA = (lane & ~3) + (q >> 1);
    const int srcB = srcA + 2;
    const bool odd = q & 1;

    stage(0, 0);
    for (int kt = 0; kt < NT; kt++) {
        int cur = kt & 1;
        if (kt + 1 < NT) { stage(cur ^ 1, kt + 1); cpa_wait<1>(); }
        else             { cpa_wait<0>(); }
        __syncthreads();
        const float* kb = Kb + cur * 64 * SK;
        const float* vb = Vb + cur * 64 * SV;

        float s[2][8][4];
#pragma unroll
        for (int mt = 0; mt < 2; mt++)
#pragma unroll
            for (int nt = 0; nt < 8; nt++)
#pragma unroll
                for (int i = 0; i < 4; i++) s[mt][nt][i] = 0.0f;
#pragma unroll
        for (int kc = 0; kc < 8; kc++) {
            unsigned bf[8][2];
#pragma unroll
            for (int nt = 0; nt < 8; nt++) {
                bf[nt][0] = __float_as_uint(kb[(nt * 8 + g) * SK + kc * 8 + q]);
                bf[nt][1] = __float_as_uint(kb[(nt * 8 + g) * SK + kc * 8 + q + 4]);
            }
#pragma unroll
            for (int mt = 0; mt < 2; mt++) {
                int r = qr + mt * 16;
                unsigned af[4];
                af[0] = __float_as_uint(Qs[(r + g)     * SQ + kc * 8 + q]);
                af[1] = __float_as_uint(Qs[(r + g + 8) * SQ + kc * 8 + q]);
                af[2] = __float_as_uint(Qs[(r + g)     * SQ + kc * 8 + q + 4]);
                af[3] = __float_as_uint(Qs[(r + g + 8) * SQ + kc * 8 + q + 4]);
#pragma unroll
                for (int nt = 0; nt < 8; nt++)
                    mma8(s[mt][nt], af, bf[nt]);
            }
        }

#pragma unroll
        for (int mt = 0; mt < 2; mt++) {
            float rm0 = -1e30f, rm1 = -1e30f;
#pragma unroll
            for (int nt = 0; nt < 8; nt++) {
                rm0 = fmaxf(rm0, fmaxf(s[mt][nt][0], s[mt][nt][1]));
                rm1 = fmaxf(rm1, fmaxf(s[mt][nt][2], s[mt][nt][3]));
            }
            rm0 = fmaxf(rm0, __shfl_xor_sync(0xffffffffu, rm0, 1));
            rm0 = fmaxf(rm0, __shfl_xor_sync(0xffffffffu, rm0, 2));
            rm1 = fmaxf(rm1, __shfl_xor_sync(0xffffffffu, rm1, 1));
            rm1 = fmaxf(rm1, __shfl_xor_sync(0xffffffffu, rm1, 2));
            float mn0 = fmaxf(m0[mt], rm0), mn1 = fmaxf(m1[mt], rm1);
            float c0 = __expf(m0[mt] - mn0), c1 = __expf(m1[mt] - mn1);
            m0[mt] = mn0; m1[mt] = mn1;
            float rs0 = 0.0f, rs1 = 0.0f;
#pragma unroll
            for (int nt = 0; nt < 8; nt++) {
                s[mt][nt][0] = __expf(s[mt][nt][0] - mn0);
                s[mt][nt][1] = __expf(s[mt][nt][1] - mn0);
                s[mt][nt][2] = __expf(s[mt][nt][2] - mn1);
                s[mt][nt][3] = __expf(s[mt][nt][3] - mn1);
                rs0 += s[mt][nt][0] + s[mt][nt][1];
                rs1 += s[mt][nt][2] + s[mt][nt][3];
            }
            rs0 += __shfl_xor_sync(0xffffffffu, rs0, 1);
            rs0 += __shfl_xor_sync(0xffffffffu, rs0, 2);
            rs1 += __shfl_xor_sync(0xffffffffu, rs1, 1);
            rs1 += __shfl_xor_sync(0xffffffffu, rs1, 2);
            l0[mt] = l0[mt] * c0 + rs0;
            l1[mt] = l1[mt] * c1 + rs1;
#pragma unroll
            for (int nt = 0; nt < 8; nt++) {
                o[mt][nt][0] *= c0; o[mt][nt][1] *= c0;
                o[mt][nt][2] *= c1; o[mt][nt][3] *= c1;
            }
        }

#pragma unroll
        for (int kc = 0; kc < 8; kc++) {
            unsigned bfv[8][2];
#pragma unroll
            for (int nt = 0; nt < 8; nt++) {
                bfv[nt][0] = __float_as_uint(vb[(kc * 8 + q)     * SV + nt * 8 + g]);
                bfv[nt][1] = __float_as_uint(vb[(kc * 8 + q + 4) * SV + nt * 8 + g]);
            }
#pragma unroll
            for (int mt = 0; mt < 2; mt++) {
                float e0 = __shfl_sync(0xffffffffu, s[mt][kc][0], srcA);
                float e1 = __shfl_sync(0xffffffffu, s[mt][kc][1], srcA);
                float e2 = __shfl_sync(0xffffffffu, s[mt][kc][2], srcA);
                float e3 = __shfl_sync(0xffffffffu, s[mt][kc][3], srcA);
                float f0 = __shfl_sync(0xffffffffu, s[mt][kc][0], srcB);
                float f1 = __shfl_sync(0xffffffffu, s[mt][kc][1], srcB);
                float f2 = __shfl_sync(0xffffffffu, s[mt][kc][2], srcB);
                float f3 = __shfl_sync(0xffffffffu, s[mt][kc][3], srcB);
                unsigned af[4];
                af[0] = f2t(odd ? e1 : e0);
                af[1] = f2t(odd ? e3 : e2);
                af[2] = f2t(odd ? f1 : f0);
                af[3] = f2t(odd ? f3 : f2);
#pragma unroll
                for (int nt = 0; nt < 8; nt++)
                    mma8(o[mt][nt], af, bfv[nt]);
            }
        }
        __syncthreads();
    }

    // epilogue
    int b = bh >> 4, h = bh & 15;
#pragma unroll
    for (int mt = 0; mt < 2; mt++) {
        float il0 = 1.0f / l0[mt], il1 = 1.0f / l1[mt];
        int r0 = qt * 128 + qr + mt * 16 + g;
#pragma unroll
        for (int nt = 0; nt < 8; nt++) {
            int cc = h * DH + nt * 8 + 2 * q;
            *(float2*)(out + (size_t)(b * SEQ + r0) * INNER + cc) =
                make_float2(o[mt][nt][0] * il0, o[mt][nt][1] * il0);
            *(float2*)(out + (size_t)(b * SEQ + r0 + 8) * INNER + cc) =
                make_float2(o[mt][nt][2] * il1, o[mt][nt][3] * il1);
        }
    }
}

// ---------------- launch ----------------
extern "C" void kernel_launch(void* const* d_in, const int* in_sizes, int n_in,
                              void* d_out, int out_size) {
    const float* x       = (const float*)d_in[0];
    const float* w_qkv   = (const float*)d_in[1];
    const float* w_fproj = (const float*)d_in[2];
    const float* b_fproj = (const float*)d_in[3];
    const float* w_out   = (const float*)d_in[4];
    const float* b_out   = (const float*)d_in[5];
    float* out = (float*)d_out;

    float *qkv_p, *attn_p;
    cudaGetSymbolAddress((void**)&qkv_p,  g_qkv);
    cudaGetSymbolAddress((void**)&attn_p, g_attn);

    cudaFuncSetAttribute(gemm_tf32<false>, cudaFuncAttributeMaxDynamicSharedMemorySize, GEMM_SMEM);
    cudaFuncSetAttribute(gemm_tf32<true>,  cudaFuncAttributeMaxDynamicSharedMemorySize, GEMM_SMEM);
    cudaFuncSetAttribute(flash_tc, cudaFuncAttributeMaxDynamicSharedMemorySize, FLASH_SMEM);

    table_kernel<<<SEQ / 4, 256>>>(w_fproj, b_fproj);

    {   // QKV: [8192,3072] = x @ w_qkv^T
        dim3 grid(3 * INNER / 128, ROWS / 128);   // 24 x 64
        gemm_tf32<false><<<grid, 256, GEMM_SMEM>>>(x, w_qkv, nullptr, qkv_p, ROWS, 3 * INNER, DIM);
    }

    rope_kernel<<<(BATCH * SEQ * HEADS * DH) / 256, 256>>>();

    {   // flash attention
        dim3 grid(SEQ / 128, BH);
        flash_tc<<<grid, 128, FLASH_SMEM>>>(attn_p);
    }

    {   // out projection
        dim3 grid(DIM / 128, ROWS / 128);
        gemm_tf32<true><<<grid, 256, GEMM_SMEM>>>(attn_p, w_out, b_out, out, ROWS, DIM, INNER);
    }
}

// round 17
// speedup vs baseline: 1.0980x; 1.0030x over previous
#include <cuda_runtime.h>
#include <cuda_bf16.h>
#include <math.h>
#include <cstdint>

#define BATCH 4
#define SEQ   2048
#define DIM   1024
#define HEADS 16
#define DH    64
#define INNER 1024
#define NFREQ 16
#define ROWS  (BATCH*SEQ)     // 8192
#define BH    (BATCH*HEADS)   // 64

// ---------------- scratch ----------------
__device__ __align__(256) float g_qkv [(size_t)ROWS * 3 * INNER];
__device__ __align__(256) float g_q   [(size_t)BH * SEQ * DH];   // tf32-rounded, pre-scaled 1/8
__device__ __align__(256) float g_k   [(size_t)BH * SEQ * DH];   // tf32-rounded
__device__ __align__(256) float g_v   [(size_t)BH * SEQ * DH];   // tf32-rounded
__device__ __align__(256) float g_attn[(size_t)ROWS * INNER];
__device__ __align__(256) float g_fenc[SEQ * DH];
__device__ __align__(256) float g_sinv[SEQ * 32];
__device__ __align__(256) float g_cosv[SEQ * 32];

// ---------------- helpers ----------------
__device__ __forceinline__ unsigned f2t(float x) {
    unsigned u; asm("cvt.rna.tf32.f32 %0, %1;" : "=r"(u) : "f"(x)); return u;
}
__device__ __forceinline__ void mma8(float* c, const unsigned* a, const unsigned* b) {
    asm volatile(
        "mma.sync.aligned.m16n8k8.row.col.f32.tf32.tf32.f32 "
        "{%0,%1,%2,%3},{%4,%5,%6,%7},{%8,%9},{%0,%1,%2,%3};"
        : "+f"(c[0]), "+f"(c[1]), "+f"(c[2]), "+f"(c[3])
        : "r"(a[0]), "r"(a[1]), "r"(a[2]), "r"(a[3]), "r"(b[0]), "r"(b[1]));
}
__device__ __forceinline__ void cpa16(void* smem, const void* gmem) {
    unsigned s = (unsigned)__cvta_generic_to_shared(smem);
    asm volatile("cp.async.cg.shared.global [%0], [%1], 16;" :: "r"(s), "l"(gmem));
}
__device__ __forceinline__ void cpa_commit() { asm volatile("cp.async.commit_group;"); }
template<int N> __device__ __forceinline__ void cpa_wait() {
    asm volatile("cp.async.wait_group %0;" :: "n"(N));
}

// ---------------- table kernel (4 positions per 256-thread block) ----------------
__global__ void __launch_bounds__(256)
table_kernel(const float* __restrict__ w_fproj,
             const float* __restrict__ b_fproj) {
    int p = blockIdx.x * 4 + (threadIdx.x >> 6);
    int d = threadIdx.x & 63;
    float fp = (float)p;
    float acc = b_fproj[d];
#pragma unroll
    for (int j = 0; j < NFREQ; j++) {
        float s = sinf(fp * (float)(j + 1));
        float c = cosf(fp * (float)(j + 1));
        acc += s * w_fproj[d * (2 * NFREQ) + j] + c * w_fproj[d * (2 * NFREQ) + NFREQ + j];
    }
    g_fenc[p * DH + d] = acc;
    if (d < 32) {
        float freq = powf(10000.0f, -(float)d / 32.0f);
        float ang = fp * freq;
        g_sinv[p * 32 + d] = sinf(ang);
        g_cosv[p * 32 + d] = cosf(ang);
    }
}

// ---------------- RoPE v2: vectorized, 4 elements per thread ----------------
// t = ((b*SEQ + n)*HEADS + h)*16 + j ; thread owns d = 4j .. 4j+3
__global__ void __launch_bounds__(256)
rope_kernel() {
    int t = blockIdx.x * 256 + threadIdx.x;        // 0 .. 2097151
    int j = t & 15;
    int h = (t >> 4) & 15;
    int n = (t >> 8) & 2047;
    int b = t >> 19;
    const float* row = g_qkv + (size_t)(b * SEQ + n) * (3 * INNER);
    const int col = h * DH + 4 * j;

    // table values (shared by the 4 lanes)
    float2 c2 = *(const float2*)(g_cosv + n * 32 + 2 * j);
    float2 s2 = *(const float2*)(g_sinv + n * 32 + 2 * j);
    float4 fe = *(const float4*)(g_fenc + n * DH + 4 * j);
    float cosv[4] = {c2.x, c2.x, c2.y, c2.y};
    float sinv[4] = {s2.x, s2.x, s2.y, s2.y};
    float fev[4]  = {fe.x, fe.y, fe.z, fe.w};

    // partner offsets within the head (two aligned float4s)
    int pbase = (j < 8) ? (h * DH + 8 * j) : (h * DH + 8 * (j - 8));

    size_t o = ((size_t)(b * HEADS + h) * SEQ + n) * DH + 4 * j;

    // ---- Q ----
    {
        float4 mv = *(const float4*)(row + col);
        float4 pa = *(const float4*)(row + pbase);
        float4 pb = *(const float4*)(row + pbase + 4);
        float m[4] = {mv.x, mv.y, mv.z, mv.w};
        float p[4];
        if (j < 8) { p[0] = pa.y; p[1] = pa.w; p[2] = pb.y; p[3] = pb.w; }
        else       { p[0] = pa.x; p[1] = pa.z; p[2] = pb.x; p[3] = pb.z; }
        float sg = (j < 8) ? -1.0f : 1.0f;
        float4 r;
        r.x = __uint_as_float(f2t(0.125f * (m[0] * cosv[0] + sg * p[0] * sinv[0] + fev[0])));
        r.y = __uint_as_float(f2t(0.125f * (m[1] * cosv[1] + sg * p[1] * sinv[1] + fev[1])));
        r.z = __uint_as_float(f2t(0.125f * (m[2] * cosv[2] + sg * p[2] * sinv[2] + fev[2])));
        r.w = __uint_as_float(f2t(0.125f * (m[3] * cosv[3] + sg * p[3] * sinv[3] + fev[3])));
        *(float4*)(g_q + o) = r;
    }
    // ---- K ----
    {
        const float* rk = row + INNER;
        float4 mv = *(const float4*)(rk + col);
        float4 pa = *(const float4*)(rk + pbase);
        float4 pb = *(const float4*)(rk + pbase + 4);
        float m[4] = {mv.x, mv.y, mv.z, mv.w};
        float p[4];
        if (j < 8) { p[0] = pa.y; p[1] = pa.w; p[2] = pb.y; p[3] = pb.w; }
        else       { p[0] = pa.x; p[1] = pa.z; p[2] = pb.x; p[3] = pb.z; }
        float sg = (j < 8) ? -1.0f : 1.0f;
        float4 r;
        r.x = __uint_as_float(f2t(m[0] * cosv[0] + sg * p[0] * sinv[0] + fev[0]));
        r.y = __uint_as_float(f2t(m[1] * cosv[1] + sg * p[1] * sinv[1] + fev[1]));
        r.z = __uint_as_float(f2t(m[2] * cosv[2] + sg * p[2] * sinv[2] + fev[2]));
        r.w = __uint_as_float(f2t(m[3] * cosv[3] + sg * p[3] * sinv[3] + fev[3]));
        *(float4*)(g_k + o) = r;
    }
    // ---- V ----
    {
        float4 mv = *(const float4*)(row + 2 * INNER + col);
        float4 r;
        r.x = __uint_as_float(f2t(mv.x));
        r.y = __uint_as_float(f2t(mv.y));
        r.z = __uint_as_float(f2t(mv.z));
        r.w = __uint_as_float(f2t(mv.w));
        *(float4*)(g_v + o) = r;
    }
}

// ---------------- tf32 GEMM, 128x128x32, cp.async double-buffered (R16-proven) ----------------
#define GS 36
#define GEMM_SMEM (2 * 2 * 128 * GS * 4)   // 73728 B -> 2 blocks/SM

template<bool BIAS>
__global__ void __launch_bounds__(256, 2)
gemm_tf32(const float* __restrict__ A, const float* __restrict__ Bw,
          const float* __restrict__ bias, float* __restrict__ C,
          int M, int N, int K) {
    extern __shared__ float gsm[];
    float* As = gsm;
    float* Bs = gsm + 2 * 128 * GS;
    const int tid = threadIdx.x;
    const int lane = tid & 31, wid = tid >> 5;
    const int g = lane >> 2, q = lane & 3;
    const int wr = wid >> 1, wc = wid & 1;
    const int bm = blockIdx.y * 128, bn = blockIdx.x * 128;
    const int lrow = tid >> 3, lcol = (tid & 7) * 4;

    float acc[2][8][4];
#pragma unroll
    for (int mt = 0; mt < 2; mt++)
#pragma unroll
        for (int nt = 0; nt < 8; nt++)
#pragma unroll
            for (int i = 0; i < 4; i++) acc[mt][nt][i] = 0.0f;

    auto stage = [&](int buf, int k0) {
        float* ab = As + buf * 128 * GS;
        float* bb = Bs + buf * 128 * GS;
#pragma unroll
        for (int j = 0; j < 4; j++) {
            int row = lrow + j * 32;
            cpa16(ab + row * GS + lcol, A  + (size_t)(bm + row) * K + k0 + lcol);
            cpa16(bb + row * GS + lcol, Bw + (size_t)(bn + row) * K + k0 + lcol);
        }
        cpa_commit();
    };

    stage(0, 0);
    for (int k0 = 0; k0 < K; k0 += 32) {
        int cur = (k0 >> 5) & 1;
        if (k0 + 32 < K) { stage(cur ^ 1, k0 + 32); cpa_wait<1>(); }
        else             { cpa_wait<0>(); }
        __syncthreads();
        const float* ab = As + cur * 128 * GS;
        const float* bb = Bs + cur * 128 * GS;
#pragma unroll
        for (int ks = 0; ks < 4; ks++) {
            unsigned af[2][4], bf[8][2];
#pragma unroll
            for (int mt = 0; mt < 2; mt++) {
                int r = wr * 32 + mt * 16;
                af[mt][0] = f2t(ab[(r + g)     * GS + ks * 8 + q]);
                af[mt][1] = f2t(ab[(r + g + 8) * GS + ks * 8 + q]);
                af[mt][2] = f2t(ab[(r + g)     * GS + ks * 8 + q + 4]);
                af[mt][3] = f2t(ab[(r + g + 8) * GS + ks * 8 + q + 4]);
            }
#pragma unroll
            for (int nt = 0; nt < 8; nt++) {
                int c = wc * 64 + nt * 8;
                bf[nt][0] = f2t(bb[(c + g) * GS + ks * 8 + q]);
                bf[nt][1] = f2t(bb[(c + g) * GS + ks * 8 + q + 4]);
            }
#pragma unroll
            for (int mt = 0; mt < 2; mt++)
#pragma unroll
                for (int nt = 0; nt < 8; nt++)
                    mma8(acc[mt][nt], af[mt], bf[nt]);
        }
        __syncthreads();
    }

#pragma unroll
    for (int mt = 0; mt < 2; mt++) {
        int r = bm + wr * 32 + mt * 16 + g;
#pragma unroll
        for (int nt = 0; nt < 8; nt++) {
            int cc = bn + wc * 64 + nt * 8 + 2 * q;
            float b0 = 0.0f, b1 = 0.0f;
            if (BIAS) { b0 = bias[cc]; b1 = bias[cc + 1]; }
            *(float2*)(C + (size_t)r * N + cc) =
                make_float2(acc[mt][nt][0] + b0, acc[mt][nt][1] + b1);
            *(float2*)(C + (size_t)(r + 8) * N + cc) =
                make_float2(acc[mt][nt][2] + b0, acc[mt][nt][3] + b1);
        }
    }
}

// ---------------- flash attention v5 (exact R6/R15/R16 kernel) ----------------
#define SQ 68
#define SK 68
#define SV 72
#define NT (SEQ / 64)
#define FLASH_SMEM ((128*SQ + 2*64*SK + 2*64*SV) * 4)   // 106496 B

__global__ void __launch_bounds__(128, 2)
flash_tc(float* __restrict__ out) {
    extern __shared__ char smraw[];
    float* Qs = (float*)smraw;
    float* Kb = (float*)(smraw + 128 * SQ * 4);
    float* Vb = Kb + 2 * 64 * SK;

    const int tid = threadIdx.x, lane = tid & 31, wid = tid >> 5;
    const int g = lane >> 2, q = lane & 3;
    const int bh = blockIdx.y, qt = blockIdx.x;
    const size_t base = (size_t)bh * SEQ * DH;
    const float* qg = g_q + base + (size_t)qt * 128 * DH;
    const float* kg0 = g_k + base;
    const float* vg0 = g_v + base;
    const int lrow = tid >> 4, lcol = (tid & 15) * 4;

#pragma unroll
    for (int j = 0; j < 16; j++) {
        int row = lrow + j * 8;
        cpa16(Qs + row * SQ + lcol, qg + row * DH + lcol);
    }
    cpa_commit();

    auto stage = [&](int buf, int kt) {
        float* kb = Kb + buf * 64 * SK;
        float* vb = Vb + buf * 64 * SV;
        const float* kg = kg0 + (size_t)kt * 64 * DH;
        const float* vg = vg0 + (size_t)kt * 64 * DH;
#pragma unroll
        for (int j = 0; j < 8; j++) {
            int row = lrow + j * 8;
            cpa16(kb + row * SK + lcol, kg + row * DH + lcol);
            cpa16(vb + row * SV + lcol, vg + row * DH + lcol);
        }
        cpa_commit();
    };

    float o[2][8][4];
#pragma unroll
    for (int mt = 0; mt < 2; mt++)
#pragma unroll
        for (int nt = 0; nt < 8; nt++)
#pragma unroll
            for (int i = 0; i < 4; i++) o[mt][nt][i] = 0.0f;
    float m0[2] = {-1e30f, -1e30f}, m1[2] = {-1e30f, -1e30f};
    float l0[2] = {0.0f, 0.0f},     l1[2] = {0.0f, 0.0f};
    const int qr = wid * 32;
    const int srcA = (lane & ~3) + (q >> 1);
    const int srcB = srcA + 2;
    const bool odd = q & 1;

    stage(0, 0);
    for (int kt = 0; kt < NT; kt++) {
        int cur = kt & 1;
        if (kt + 1 < NT) { stage(cur ^ 1, kt + 1); cpa_wait<1>(); }
        else             { cpa_wait<0>(); }
        __syncthreads();
        const float* kb = Kb + cur * 64 * SK;
        const float* vb = Vb + cur * 64 * SV;

        float s[2][8][4];
#pragma unroll
        for (int mt = 0; mt < 2; mt++)
#pragma unroll
            for (int nt = 0; nt < 8; nt++)
#pragma unroll
                for (int i = 0; i < 4; i++) s[mt][nt][i] = 0.0f;
#pragma unroll
        for (int kc = 0; kc < 8; kc++) {
            unsigned bf[8][2];
#pragma unroll
            for (int nt = 0; nt < 8; nt++) {
                bf[nt][0] = __float_as_uint(kb[(nt * 8 + g) * SK + kc * 8 + q]);
                bf[nt][1] = __float_as_uint(kb[(nt * 8 + g) * SK + kc * 8 + q + 4]);
            }
#pragma unroll
            for (int mt = 0; mt < 2; mt++) {
                int r = qr + mt * 16;
                unsigned af[4];
                af[0] = __float_as_uint(Qs[(r + g)     * SQ + kc * 8 + q]);
                af[1] = __float_as_uint(Qs[(r + g + 8) * SQ + kc * 8 + q]);
                af[2] = __float_as_uint(Qs[(r + g)     * SQ + kc * 8 + q + 4]);
                af[3] = __float_as_uint(Qs[(r + g + 8) * SQ + kc * 8 + q + 4]);
#pragma unroll
                for (int nt = 0; nt < 8; nt++)
                    mma8(s[mt][nt], af, bf[nt]);
            }
        }

#pragma unroll
        for (int mt = 0; mt < 2; mt++) {
            float rm0 = -1e30f, rm1 = -1e30f;
#pragma unroll
            for (int nt = 0; nt < 8; nt++) {
                rm0 = fmaxf(rm0, fmaxf(s[mt][nt][0], s[mt][nt][1]));
                rm1 = fmaxf(rm1, fmaxf(s[mt][nt][2], s[mt][nt][3]));
            }
            rm0 = fmaxf(rm0, __shfl_xor_sync(0xffffffffu, rm0, 1));
            rm0 = fmaxf(rm0, __shfl_xor_sync(0xffffffffu, rm0, 2));
            rm1 = fmaxf(rm1, __shfl_xor_sync(0xffffffffu, rm1, 1));
            rm1 = fmaxf(rm1, __shfl_xor_sync(0xffffffffu, rm1, 2));
            float mn0 = fmaxf(m0[mt], rm0), mn1 = fmaxf(m1[mt], rm1);
            float c0 = __expf(m0[mt] - mn0), c1 = __expf(m1[mt] - mn1);
            m0[mt] = mn0; m1[mt] = mn1;
            float rs0 = 0.0f, rs1 = 0.0f;
#pragma unroll
            for (int nt = 0; nt < 8; nt++) {
                s[mt][nt][0] = __expf(s[mt][nt][0] - mn0);
                s[mt][nt][1] = __expf(s[mt][nt][1] - mn0);
                s[mt][nt][2] = __expf(s[mt][nt][2] - mn1);
                s[mt][nt][3] = __expf(s[mt][nt][3] - mn1);
                rs0 += s[mt][nt][0] + s[mt][nt][1];
                rs1 += s[mt][nt][2] + s[mt][nt][3];
            }
            rs0 += __shfl_xor_sync(0xffffffffu, rs0, 1);
            rs0 += __shfl_xor_sync(0xffffffffu, rs0, 2);
            rs1 += __shfl_xor_sync(0xffffffffu, rs1, 1);
            rs1 += __shfl_xor_sync(0xffffffffu, rs1, 2);
            l0[mt] = l0[mt] * c0 + rs0;
            l1[mt] = l1[mt] * c1 + rs1;
#pragma unroll
            for (int nt = 0; nt < 8; nt++) {
                o[mt][nt][0] *= c0; o[mt][nt][1] *= c0;
                o[mt][nt][2] *= c1; o[mt][nt][3] *= c1;
            }
        }

#pragma unroll
        for (int kc = 0; kc < 8; kc++) {
            unsigned bfv[8][2];
#pragma unroll
            for (int nt = 0; nt < 8; nt++) {
                bfv[nt][0] = __float_as_uint(vb[(kc * 8 + q)     * SV + nt * 8 + g]);
                bfv[nt][1] = __float_as_uint(vb[(kc * 8 + q + 4) * SV + nt * 8 + g]);
            }
#pragma unroll
            for (int mt = 0; mt < 2; mt++) {
                float e0 = __shfl_sync(0xffffffffu, s[mt][kc][0], srcA);
                float e1 = __shfl_sync(0xffffffffu, s[mt][kc][1], srcA);
                float e2 = __shfl_sync(0xffffffffu, s[mt][kc][2], srcA);
                float e3 = __shfl_sync(0xffffffffu, s[mt][kc][3], srcA);
                float f0 = __shfl_sync(0xffffffffu, s[mt][kc][0], srcB);
                float f1 = __shfl_sync(0xffffffffu, s[mt][kc][1], srcB);
                float f2 = __shfl_sync(0xffffffffu, s[mt][kc][2], srcB);
                float f3 = __shfl_sync(0xffffffffu, s[mt][kc][3], srcB);
                unsigned af[4];
                af[0] = f2t(odd ? e1 : e0);
                af[1] = f2t(odd ? e3 : e2);
                af[2] = f2t(odd ? f1 : f0);
                af[3] = f2t(odd ? f3 : f2);
#pragma unroll
                for (int nt = 0; nt < 8; nt++)
                    mma8(o[mt][nt], af, bfv[nt]);
            }
        }
        __syncthreads();
    }

    // epilogue
    int b = bh >> 4, h = bh & 15;
#pragma unroll
    for (int mt = 0; mt < 2; mt++) {
        float il0 = 1.0f / l0[mt], il1 = 1.0f / l1[mt];
        int r0 = qt * 128 + qr + mt * 16 + g;
#pragma unroll
        for (int nt = 0; nt < 8; nt++) {
            int cc = h * DH + nt * 8 + 2 * q;
            *(float2*)(out + (size_t)(b * SEQ + r0) * INNER + cc) =
                make_float2(o[mt][nt][0] * il0, o[mt][nt][1] * il0);
            *(float2*)(out + (size_t)(b * SEQ + r0 + 8) * INNER + cc) =
                make_float2(o[mt][nt][2] * il1, o[mt][nt][3] * il1);
        }
    }
}

// ---------------- launch ----------------
extern "C" void kernel_launch(void* const* d_in, const int* in_sizes, int n_in,
                              void* d_out, int out_size) {
    const float* x       = (const float*)d_in[0];
    const float* w_qkv   = (const float*)d_in[1];
    const float* w_fproj = (const float*)d_in[2];
    const float* b_fproj = (const float*)d_in[3];
    const float* w_out   = (const float*)d_in[4];
    const float* b_out   = (const float*)d_in[5];
    float* out = (float*)d_out;

    float *qkv_p, *attn_p;
    cudaGetSymbolAddress((void**)&qkv_p,  g_qkv);
    cudaGetSymbolAddress((void**)&attn_p, g_attn);

    cudaFuncSetAttribute(gemm_tf32<false>, cudaFuncAttributeMaxDynamicSharedMemorySize, GEMM_SMEM);
    cudaFuncSetAttribute(gemm_tf32<true>,  cudaFuncAttributeMaxDynamicSharedMemorySize, GEMM_SMEM);
    cudaFuncSetAttribute(flash_tc, cudaFuncAttributeMaxDynamicSharedMemorySize, FLASH_SMEM);

    table_kernel<<<SEQ / 4, 256>>>(w_fproj, b_fproj);

    {   // QKV: [8192,3072] = x @ w_qkv^T
        dim3 grid(3 * INNER / 128, ROWS / 128);   // 24 x 64
        gemm_tf32<false><<<grid, 256, GEMM_SMEM>>>(x, w_qkv, nullptr, qkv_p, ROWS, 3 * INNER, DIM);
    }

    // rope v2: 4 elements/thread -> 2M/4 = 524288 threads
    rope_kernel<<<(BATCH * SEQ * HEADS * 16) / 256, 256>>>();

    {   // flash attention
        dim3 grid(SEQ / 128, BH);
        flash_tc<<<grid, 128, FLASH_SMEM>>>(attn_p);
    }

    {   // out projection
        dim3 grid(DIM / 128, ROWS / 128);
        gemm_tf32<true><<<grid, 256, GEMM_SMEM>>>(attn_p, w_out, b_out, out, ROWS, DIM, INNER);
    }
}